// round 1
// baseline (speedup 1.0000x reference)
#include <cuda_runtime.h>
#include <cuda_bf16.h>
#include <math.h>

// ---------------------------------------------------------------------------
// SynthesisLayer: styles = w@A^T/sqrt(512)+b ; modulate-demodulate conv3x3 on
// 2x-upsampled input ; noise + bias + lrelu*sqrt(2).
//
// Restructured:
//   - modulate INPUT by style, demodulate OUTPUT by dcoef (weights batch-shared)
//   - fold upfirdn(up2, [1,3,3,1]) + conv3x3 into 4 phase 3x3 kernels on the
//     32x32 grid (no 66x66 intermediate).
// ---------------------------------------------------------------------------

#define B_      16
#define C_      512
#define HIN     32
#define RESO    64
#define KTAPS   9

__device__ float g_styles[B_ * C_];
__device__ float g_dcoef [B_ * C_];
__device__ float g_wsq   [C_ * C_];
// phase-composed weights: [phase(4)][ci(512)][k(9)][co(512)]
__device__ float g_pw    [4 * C_ * KTAPS * C_];

// ---- styles[b][j] = dot(w[b], A[j]) / sqrt(512) + bias[j] -----------------
__global__ void k_styles(const float* __restrict__ w,
                         const float* __restrict__ aw,
                         const float* __restrict__ ab) {
    int b = blockIdx.x;
    int j = threadIdx.x;
    __shared__ float ws[C_];
    ws[j] = w[b * C_ + j];
    __syncthreads();
    const float* row = aw + j * C_;
    float s = 0.f;
    #pragma unroll 8
    for (int d = 0; d < C_; d++) s += row[d] * ws[d];
    g_styles[b * C_ + j] = s * 0.04419417382415922f + ab[j];
}

// ---- wsq[co][ci] = sum over 9 taps of weight^2 ----------------------------
__global__ void k_wsq(const float* __restrict__ weight) {
    int idx = blockIdx.x * 256 + threadIdx.x;   // idx = co*512+ci
    const float* p = weight + idx * KTAPS;
    float s = 0.f;
    #pragma unroll
    for (int i = 0; i < KTAPS; i++) s += p[i] * p[i];
    g_wsq[idx] = s;
}

// ---- dcoef[b][co] = rsqrt( sum_ci styles^2 * wsq + 1e-8 ) -----------------
__global__ void k_dcoef() {
    int b  = blockIdx.x;
    int co = threadIdx.x;
    __shared__ float s2[C_];
    float st = g_styles[b * C_ + co];
    s2[co] = st * st;
    __syncthreads();
    const float* wq = g_wsq + co * C_;
    float s = 0.f;
    #pragma unroll 8
    for (int d = 0; d < C_; d++) s += wq[d] * s2[d];
    g_dcoef[b * C_ + co] = rsqrtf(s + 1e-8f);
}

// ---- phase-composed 3x3 kernels -------------------------------------------
// P[ry,rx][dyi,dxi] = sum_{sy,sx} w[2-sy][2-sx] * c[uy]*c[ux]/16,
//   u = 2*d_idx + 1 - r - s, valid when 0 <= u < 4, c = {1,3,3,1}.
__global__ void k_pw(const float* __restrict__ weight) {
    int ci = blockIdx.x;
    int co = threadIdx.x;
    const float* p = weight + (co * C_ + ci) * KTAPS;
    float wgt[3][3];
    #pragma unroll
    for (int sy = 0; sy < 3; sy++)
        #pragma unroll
        for (int sx = 0; sx < 3; sx++) wgt[sy][sx] = p[sy * 3 + sx];
    const float cc[4] = {1.f, 3.f, 3.f, 1.f};
    #pragma unroll
    for (int ry = 0; ry < 2; ry++)
    #pragma unroll
    for (int rx = 0; rx < 2; rx++) {
        int ph = ry * 2 + rx;
        #pragma unroll
        for (int dyi = 0; dyi < 3; dyi++)
        #pragma unroll
        for (int dxi = 0; dxi < 3; dxi++) {
            float v = 0.f;
            #pragma unroll
            for (int sy = 0; sy < 3; sy++) {
                int uy = 2 * dyi + 1 - ry - sy;
                if (uy < 0 || uy > 3) continue;
                #pragma unroll
                for (int sx = 0; sx < 3; sx++) {
                    int ux = 2 * dxi + 1 - rx - sx;
                    if (ux < 0 || ux > 3) continue;
                    v += wgt[2 - sy][2 - sx] * cc[uy] * cc[ux];
                }
            }
            g_pw[((ph * C_ + ci) * KTAPS + dyi * 3 + dxi) * C_ + co] = v * 0.0625f;
        }
    }
}

// ---- main conv: per (b, phase): y_phase = conv3x3(xs, Pw) * dcoef + epi ---
// Block: 64 co  x  (8 q-rows x 32 q-cols). 256 threads, 8co x 8row per thread.
#define MT  64   // co tile
#define QYT 8    // q rows per block
#define CHK 8    // ci per chunk

__global__ __launch_bounds__(256, 2)
void k_conv(const float* __restrict__ x,
            const float* __restrict__ bias,
            const float* __restrict__ noise,
            const float* __restrict__ nstr,
            float* __restrict__ out) {
    __shared__ float sx[CHK][QYT + 2][HIN + 2];    // [8][10][34]
    __shared__ float sw[CHK][KTAPS][MT];           // [8][9][64]

    const int tid  = threadIdx.x;
    const int lane = tid & 31;        // q-col
    const int wid  = tid >> 5;        // co sub-tile (8 warps)
    const int qy0  = blockIdx.x * QYT;
    const int co0  = blockIdx.y * MT;
    const int bz   = blockIdx.z;
    const int b    = bz >> 2;
    const int ph   = bz & 3;
    const int ry   = ph >> 1, rx = ph & 1;

    float acc[8][8];
    #pragma unroll
    for (int j = 0; j < 8; j++)
        #pragma unroll
        for (int r = 0; r < 8; r++) acc[j][r] = 0.f;

    const float* xb = x + (long)b * C_ * HIN * HIN;
    float* swf = &sw[0][0][0];

    for (int ci0 = 0; ci0 < C_; ci0 += CHK) {
        // load modulated input tile (zero-padded by 1)
        for (int t = tid; t < CHK * (QYT + 2) * (HIN + 2); t += 256) {
            int ci  = t / ((QYT + 2) * (HIN + 2));
            int rem = t - ci * ((QYT + 2) * (HIN + 2));
            int row = rem / (HIN + 2);
            int col = rem - row * (HIN + 2);
            int gy  = qy0 - 1 + row;
            int gx  = col - 1;
            float v = 0.f;
            if ((unsigned)gy < (unsigned)HIN && (unsigned)gx < (unsigned)HIN)
                v = xb[((ci0 + ci) * HIN + gy) * HIN + gx] *
                    g_styles[b * C_ + ci0 + ci];
            sx[ci][row][col] = v;
        }
        // load phase weights tile
        for (int t = tid; t < CHK * KTAPS * MT; t += 256) {
            int ci = t / (KTAPS * MT);
            int r2 = t - ci * (KTAPS * MT);
            int k  = r2 >> 6;
            int c  = r2 & 63;
            swf[t] = g_pw[(long)(ph * C_ + ci0 + ci) * (KTAPS * C_) + k * C_ + co0 + c];
        }
        __syncthreads();

        #pragma unroll 1
        for (int ci = 0; ci < CHK; ci++) {
            #pragma unroll
            for (int k = 0; k < KTAPS; k++) {
                const int dy = k / 3, dx = k - (k / 3) * 3;
                float4 w0 = *(const float4*)&sw[ci][k][wid * 8];
                float4 w1 = *(const float4*)&sw[ci][k][wid * 8 + 4];
                float xv[8];
                #pragma unroll
                for (int r = 0; r < 8; r++) xv[r] = sx[ci][r + dy][lane + dx];
                float wv[8] = {w0.x, w0.y, w0.z, w0.w, w1.x, w1.y, w1.z, w1.w};
                #pragma unroll
                for (int j = 0; j < 8; j++)
                    #pragma unroll
                    for (int r = 0; r < 8; r++)
                        acc[j][r] += wv[j] * xv[r];
            }
        }
        __syncthreads();
    }

    // epilogue: demod, noise, bias, lrelu*sqrt(2)
    const float ns = *nstr;
    const int ox = 2 * lane + rx;
    float nz[8];
    #pragma unroll
    for (int r = 0; r < 8; r++) {
        int oy = 2 * (qy0 + r) + ry;
        nz[r] = noise[oy * RESO + ox] * ns;
    }
    #pragma unroll
    for (int j = 0; j < 8; j++) {
        int co = co0 + wid * 8 + j;
        float dc = g_dcoef[b * C_ + co];
        float bv = bias[co];
        float* op = out + ((long)(b * C_ + co) * RESO) * RESO + ox;
        #pragma unroll
        for (int r = 0; r < 8; r++) {
            int oy = 2 * (qy0 + r) + ry;
            float v = acc[j][r] * dc + nz[r] + bv;
            v = (v >= 0.f ? v : 0.2f * v) * 1.4142135623730951f;
            op[oy * RESO] = v;
        }
    }
}

extern "C" void kernel_launch(void* const* d_in, const int* in_sizes, int n_in,
                              void* d_out, int out_size) {
    const float* x      = (const float*)d_in[0];
    const float* w      = (const float*)d_in[1];
    const float* aw     = (const float*)d_in[2];
    const float* ab     = (const float*)d_in[3];
    const float* weight = (const float*)d_in[4];
    const float* bias   = (const float*)d_in[5];
    const float* noise  = (const float*)d_in[6];
    const float* nstr   = (const float*)d_in[7];
    float* out = (float*)d_out;

    k_styles<<<B_, C_>>>(w, aw, ab);
    k_wsq<<<(C_ * C_) / 256, 256>>>(weight);
    k_pw<<<C_, C_>>>(weight);
    k_dcoef<<<B_, C_>>>();
    k_conv<<<dim3(HIN / QYT, C_ / MT, B_ * 4), 256>>>(x, bias, noise, nstr, out);
}

// round 3
// speedup vs baseline: 5.3091x; 5.3091x over previous
#include <cuda_runtime.h>
#include <cuda.h>
#include <cstdint>

// ---------------------------------------------------------------------------
// SynthesisLayer on GB300 — mma.sync tf32 implicit GEMM (portable PTX; the
// harness targets compute_103 which rejects tcgen05).
//   styles = w@A^T/sqrt(512)+b ; xs = x*style (tf32-rounded) ;
//   per (b,phase): C[co][pix] = sum_{tap,ci} PW[ph][tap][co][ci]*xs[ci][pix'] ;
//   epilogue: *dcoef + noise + bias, lrelu*sqrt(2).
// ---------------------------------------------------------------------------

#define B_    16
#define C_    512
#define HIN   32
#define RESO  64

__device__ float g_styles[B_ * C_];
__device__ float g_dcoef [B_ * C_];
__device__ float g_pw    [4 * 9 * C_ * C_];              // [ph][tap][co][ci], tf32-rounded
__device__ float g_xs    [(size_t)B_ * C_ * HIN * HIN];  // modulated input, tf32-rounded

__device__ __forceinline__ float to_tf32(float x) {
    float y;
    asm("cvt.rna.tf32.f32 %0, %1;" : "=f"(y) : "f"(x));
    return y;
}
__device__ __forceinline__ uint32_t smem_u32(const void* p) {
    uint32_t a;
    asm("{ .reg .u64 t; cvta.to.shared.u64 t, %1; cvt.u32.u64 %0, t; }"
        : "=r"(a) : "l"(p));
    return a;
}
__device__ __forceinline__ void cp16(uint32_t dst, const void* src) {
    asm volatile("cp.async.cg.shared.global [%0], [%1], 16;" :: "r"(dst), "l"(src));
}
__device__ __forceinline__ void cp4z(uint32_t dst, const void* src, bool valid) {
    int sz = valid ? 4 : 0;
    asm volatile("cp.async.ca.shared.global [%0], [%1], 4, %2;"
                 :: "r"(dst), "l"(src), "r"(sz));
}
#define CP_COMMIT() asm volatile("cp.async.commit_group;" ::: "memory")
#define CP_WAIT0()  asm volatile("cp.async.wait_group 0;" ::: "memory")

__device__ __forceinline__ void mma8(float* d, const float* a, const float* b) {
    asm volatile(
        "mma.sync.aligned.m16n8k8.row.col.f32.tf32.tf32.f32 "
        "{%0,%1,%2,%3}, {%4,%5,%6,%7}, {%8,%9}, {%0,%1,%2,%3};"
        : "+f"(d[0]), "+f"(d[1]), "+f"(d[2]), "+f"(d[3])
        : "r"(__float_as_uint(a[0])), "r"(__float_as_uint(a[1])),
          "r"(__float_as_uint(a[2])), "r"(__float_as_uint(a[3])),
          "r"(__float_as_uint(b[0])), "r"(__float_as_uint(b[1])));
}

// ======================= setup kernels (warp-per-output) ===================
__global__ void k_styles(const float* __restrict__ w,
                         const float* __restrict__ aw,
                         const float* __restrict__ ab) {
    int gw = blockIdx.x * 8 + (threadIdx.x >> 5);  // warp id = (b, j)
    int lane = threadIdx.x & 31;
    int b = gw >> 9, j = gw & 511;
    const float4* ar = (const float4*)(aw + (size_t)j * C_);
    const float4* wr = (const float4*)(w + (size_t)b * C_);
    float s = 0.f;
    #pragma unroll
    for (int i = 0; i < 4; i++) {
        float4 a = ar[lane + 32 * i], x = wr[lane + 32 * i];
        s += a.x * x.x + a.y * x.y + a.z * x.z + a.w * x.w;
    }
    #pragma unroll
    for (int o = 16; o; o >>= 1) s += __shfl_xor_sync(~0u, s, o);
    if (lane == 0) g_styles[gw] = s * 0.04419417382415922f + ab[j];
}

// dcoef[b][co] = rsqrt( sum_ci styles[b][ci]^2 * wsq[co][ci] + 1e-8 )
__global__ void k_dcoef(const float* __restrict__ weight) {
    int gw = blockIdx.x * 8 + (threadIdx.x >> 5);  // (b, co)
    int lane = threadIdx.x & 31;
    int b = gw >> 9, co = gw & 511;
    const float* wp = weight + (size_t)co * C_ * 9;
    const float* sp = g_styles + b * C_;
    float s = 0.f;
    #pragma unroll 4
    for (int ci = lane; ci < C_; ci += 32) {
        const float* p = wp + ci * 9;
        float q = 0.f;
        #pragma unroll
        for (int i = 0; i < 9; i++) q += p[i] * p[i];
        float st = sp[ci];
        s += q * st * st;
    }
    #pragma unroll
    for (int o = 16; o; o >>= 1) s += __shfl_xor_sync(~0u, s, o);
    if (lane == 0) g_dcoef[gw] = rsqrtf(s + 1e-8f);
}

// phase-composed 3x3 kernels -> g_pw[ph][tap][co][ci], tf32-rounded
__global__ void k_pw(const float* __restrict__ weight) {
    int co = blockIdx.x, ci = threadIdx.x;
    const float* p = weight + ((size_t)co * C_ + ci) * 9;
    float wgt[3][3];
    #pragma unroll
    for (int sy = 0; sy < 3; sy++)
        #pragma unroll
        for (int sx = 0; sx < 3; sx++) wgt[sy][sx] = p[sy * 3 + sx];
    const float cc[4] = {1.f, 3.f, 3.f, 1.f};
    #pragma unroll
    for (int ry = 0; ry < 2; ry++)
    #pragma unroll
    for (int rx = 0; rx < 2; rx++) {
        int ph = ry * 2 + rx;
        #pragma unroll
        for (int dyi = 0; dyi < 3; dyi++)
        #pragma unroll
        for (int dxi = 0; dxi < 3; dxi++) {
            float v = 0.f;
            #pragma unroll
            for (int sy = 0; sy < 3; sy++) {
                int uy = 2 * dyi + 1 - ry - sy;
                if (uy < 0 || uy > 3) continue;
                #pragma unroll
                for (int sx = 0; sx < 3; sx++) {
                    int ux = 2 * dxi + 1 - rx - sx;
                    if (ux < 0 || ux > 3) continue;
                    v += wgt[2 - sy][2 - sx] * cc[uy] * cc[ux];
                }
            }
            int tap = dyi * 3 + dxi;
            g_pw[(((size_t)(ph * 9 + tap) * C_) + co) * C_ + ci] = to_tf32(v * 0.0625f);
        }
    }
}

__global__ void k_xs(const float* __restrict__ x) {
    int bc = blockIdx.x;                       // b*512+ci
    float st = g_styles[bc];
    const float4* src = (const float4*)(x + (size_t)bc * (HIN * HIN));
    float4* dst = (float4*)(g_xs + (size_t)bc * (HIN * HIN));
    float4 v = src[threadIdx.x];
    v.x = to_tf32(v.x * st); v.y = to_tf32(v.y * st);
    v.z = to_tf32(v.z * st); v.w = to_tf32(v.w * st);
    dst[threadIdx.x] = v;
}

// ======================= main MMA conv =====================================
// CTA 128co x 128pix, 8 warps (2M x 4N), warp 64x32, mma m16n8k8 tf32.
// K = 9 taps x 16 chunks of 32 ci = 144 chunks, double-buffered cp.async.
#define KC   32
#define NCH  144
#define AS   36                     // A row stride (floats): banks 4g+c distinct
#define BS   132                    // B row stride (floats): banks 4c+g distinct
#define A_FLOATS (128 * AS)         // 4608
#define B_FLOATS (KC * BS)          // 4224
#define BUF_FLOATS (A_FLOATS + B_FLOATS)
#define BUF_BYTES  (BUF_FLOATS * 4) // 35328 (16B-aligned)
#define SMEM_DYN   (2 * BUF_BYTES)

__global__ void __launch_bounds__(256, 2)
k_conv_mma(const float* __restrict__ bias,
           const float* __restrict__ noise,
           const float* __restrict__ nstr,
           float* __restrict__ out) {
    extern __shared__ float dsm[];
    const uint32_t sbase = smem_u32(dsm);

    const int tid  = threadIdx.x;
    const int lane = tid & 31;
    const int wid  = tid >> 5;
    const int wm   = (wid & 1) * 64;          // warp co offset
    const int wn   = (wid >> 1) * 32;         // warp pix offset
    const int g    = lane >> 2;               // groupID
    const int tg   = lane & 3;                // thread-in-group

    const int co0 = blockIdx.x * 128;
    const int N0  = blockIdx.y * 128;         // pixel tile base (4 q-rows)
    const int bz  = blockIdx.z;
    const int b   = bz >> 2, ph = bz & 3;
    const int ry  = ph >> 1, rx = ph & 1;
    const int qy0 = N0 >> 5;

    const float* xs_b = g_xs + (size_t)b * C_ * (HIN * HIN);

    float acc[4][4][4];
    #pragma unroll
    for (int mf = 0; mf < 4; mf++)
        #pragma unroll
        for (int nf = 0; nf < 4; nf++)
            #pragma unroll
            for (int r = 0; r < 4; r++) acc[mf][nf][r] = 0.f;

    // ---- chunk loader (cp.async into buffer p) ----
    auto load_chunk = [&](int it, int p) {
        const int tap = it >> 4;
        const int ci0 = (it & 15) * KC;
        const int dy = tap / 3, dx = tap - 3 * (tap / 3);
        const uint32_t ab = sbase + p * BUF_BYTES;
        const uint32_t bb = ab + A_FLOATS * 4;
        // A: 128 rows x 32 floats (1024 float4)
        const float* asrc = g_pw + (((size_t)(ph * 9 + tap) * C_) + co0) * C_ + ci0;
        #pragma unroll
        for (int j = 0; j < 4; j++) {
            int f4 = j * 256 + tid;
            int m = f4 >> 3, q = f4 & 7;
            cp16(ab + (uint32_t)(m * (AS * 4) + q * 16), asrc + m * C_ + q * 4);
        }
        // B: 32 k-rows x 128 pixels (scalar, zero-filled at borders)
        #pragma unroll
        for (int j = 0; j < 16; j++) {
            int e = j * 256 + tid;
            int k = e >> 7, pxn = e & 127;
            int gy = qy0 + (pxn >> 5) + dy - 1;
            int gx = (pxn & 31) + dx - 1;
            bool ok = ((unsigned)gy < (unsigned)HIN) & ((unsigned)gx < (unsigned)HIN);
            cp4z(bb + (uint32_t)((k * BS + pxn) * 4),
                 xs_b + (size_t)(ci0 + k) * (HIN * HIN) + gy * HIN + gx, ok);
        }
    };

    load_chunk(0, 0);
    CP_COMMIT();

    for (int it = 0; it < NCH; ++it) {
        const int p = it & 1;
        CP_WAIT0();
        __syncthreads();
        if (it + 1 < NCH) { load_chunk(it + 1, p ^ 1); CP_COMMIT(); }

        const float* sA = dsm + p * BUF_FLOATS;
        const float* sB = sA + A_FLOATS;
        #pragma unroll
        for (int ks = 0; ks < 4; ks++) {
            float af[4][4], bf[4][2];
            #pragma unroll
            for (int mf = 0; mf < 4; mf++) {
                int r0 = wm + mf * 16 + g;
                int c0 = ks * 8 + tg;
                af[mf][0] = sA[r0 * AS + c0];
                af[mf][1] = sA[(r0 + 8) * AS + c0];
                af[mf][2] = sA[r0 * AS + c0 + 4];
                af[mf][3] = sA[(r0 + 8) * AS + c0 + 4];
            }
            #pragma unroll
            for (int nf = 0; nf < 4; nf++) {
                int col = wn + nf * 8 + g;
                int k0 = ks * 8 + tg;
                bf[nf][0] = sB[k0 * BS + col];
                bf[nf][1] = sB[(k0 + 4) * BS + col];
            }
            #pragma unroll
            for (int mf = 0; mf < 4; mf++)
                #pragma unroll
                for (int nf = 0; nf < 4; nf++)
                    mma8(acc[mf][nf], af[mf], bf[nf]);
        }
    }

    // ---- epilogue: demod + noise + bias + lrelu*sqrt(2) ----
    const float ns = *nstr;
    int oyv[4], oxv[4];
    float nz0[4], nz1[4];
    #pragma unroll
    for (int nf = 0; nf < 4; nf++) {
        int n0 = wn + nf * 8 + 2 * tg;
        int gp = N0 + n0;
        oyv[nf] = 2 * (gp >> 5) + ry;
        oxv[nf] = 2 * (n0 & 31) + rx;
        nz0[nf] = noise[oyv[nf] * RESO + oxv[nf]] * ns;
        nz1[nf] = noise[oyv[nf] * RESO + oxv[nf] + 2] * ns;
    }
    #pragma unroll
    for (int mf = 0; mf < 4; mf++) {
        int co_a = co0 + wm + mf * 16 + g;
        int co_b = co_a + 8;
        float dca = g_dcoef[b * C_ + co_a], bva = bias[co_a];
        float dcb = g_dcoef[b * C_ + co_b], bvb = bias[co_b];
        float* oa = out + ((size_t)(b * C_ + co_a) * RESO) * RESO;
        float* ob = out + ((size_t)(b * C_ + co_b) * RESO) * RESO;
        #pragma unroll
        for (int nf = 0; nf < 4; nf++) {
            int base = oyv[nf] * RESO + oxv[nf];
            float v0 = acc[mf][nf][0] * dca + nz0[nf] + bva;
            float v1 = acc[mf][nf][1] * dca + nz1[nf] + bva;
            float v2 = acc[mf][nf][2] * dcb + nz0[nf] + bvb;
            float v3 = acc[mf][nf][3] * dcb + nz1[nf] + bvb;
            v0 = (v0 >= 0.f ? v0 : 0.2f * v0) * 1.4142135623730951f;
            v1 = (v1 >= 0.f ? v1 : 0.2f * v1) * 1.4142135623730951f;
            v2 = (v2 >= 0.f ? v2 : 0.2f * v2) * 1.4142135623730951f;
            v3 = (v3 >= 0.f ? v3 : 0.2f * v3) * 1.4142135623730951f;
            oa[base]     = v0;
            oa[base + 2] = v1;
            ob[base]     = v2;
            ob[base + 2] = v3;
        }
    }
}

// ======================= launch ============================================
extern "C" void kernel_launch(void* const* d_in, const int* in_sizes, int n_in,
                              void* d_out, int out_size) {
    const float* x      = (const float*)d_in[0];
    const float* w      = (const float*)d_in[1];
    const float* aw     = (const float*)d_in[2];
    const float* ab     = (const float*)d_in[3];
    const float* weight = (const float*)d_in[4];
    const float* bias   = (const float*)d_in[5];
    const float* noise  = (const float*)d_in[6];
    const float* nstr   = (const float*)d_in[7];
    float* out = (float*)d_out;

    static bool attr_set = false;
    if (!attr_set) {
        cudaFuncSetAttribute(k_conv_mma,
                             cudaFuncAttributeMaxDynamicSharedMemorySize, SMEM_DYN);
        attr_set = true;
    }

    k_styles<<<(B_ * C_) / 8, 256>>>(w, aw, ab);
    k_pw<<<C_, C_>>>(weight);
    k_dcoef<<<(B_ * C_) / 8, 256>>>(weight);
    k_xs<<<B_ * C_, (HIN * HIN) / 4>>>(x);
    k_conv_mma<<<dim3(4, 8, B_ * 4), 256, SMEM_DYN>>>(bias, noise, nstr, out);
}

// round 4
// speedup vs baseline: 5.9383x; 1.1185x over previous
#include <cuda_runtime.h>
#include <cuda.h>
#include <cstdint>

// ---------------------------------------------------------------------------
// SynthesisLayer on GB300 — mma.sync tf32 implicit GEMM, raw-xs smem with
// tap shifts applied at fragment-load time (no im2col redundancy).
// ---------------------------------------------------------------------------

#define B_    16
#define C_    512
#define HIN   32
#define RESO  64

__device__ float g_styles[B_ * C_];
__device__ float g_dcoef [B_ * C_];
__device__ float g_pw    [4 * 9 * C_ * C_];              // [ph][tap][co][ci], tf32-rounded
__device__ float g_xs    [(size_t)B_ * C_ * HIN * HIN];  // modulated input, tf32-rounded

__device__ __forceinline__ float to_tf32(float x) {
    float y;
    asm("cvt.rna.tf32.f32 %0, %1;" : "=f"(y) : "f"(x));
    return y;
}
__device__ __forceinline__ uint32_t smem_u32(const void* p) {
    uint32_t a;
    asm("{ .reg .u64 t; cvta.to.shared.u64 t, %1; cvt.u32.u64 %0, t; }"
        : "=r"(a) : "l"(p));
    return a;
}
__device__ __forceinline__ void cp16(uint32_t dst, const void* src) {
    asm volatile("cp.async.cg.shared.global [%0], [%1], 16;" :: "r"(dst), "l"(src));
}
__device__ __forceinline__ void cp4z(uint32_t dst, const void* src, bool valid) {
    int sz = valid ? 4 : 0;
    asm volatile("cp.async.ca.shared.global [%0], [%1], 4, %2;"
                 :: "r"(dst), "l"(src), "r"(sz));
}
#define CP_COMMIT() asm volatile("cp.async.commit_group;" ::: "memory")
#define CP_WAIT0()  asm volatile("cp.async.wait_group 0;" ::: "memory")

__device__ __forceinline__ void mma8(float* d, const float* a, const float* b) {
    asm volatile(
        "mma.sync.aligned.m16n8k8.row.col.f32.tf32.tf32.f32 "
        "{%0,%1,%2,%3}, {%4,%5,%6,%7}, {%8,%9}, {%0,%1,%2,%3};"
        : "+f"(d[0]), "+f"(d[1]), "+f"(d[2]), "+f"(d[3])
        : "r"(__float_as_uint(a[0])), "r"(__float_as_uint(a[1])),
          "r"(__float_as_uint(a[2])), "r"(__float_as_uint(a[3])),
          "r"(__float_as_uint(b[0])), "r"(__float_as_uint(b[1])));
}

// ======================= setup kernels =====================================
__global__ void k_styles(const float* __restrict__ w,
                         const float* __restrict__ aw,
                         const float* __restrict__ ab) {
    int gw = blockIdx.x * 8 + (threadIdx.x >> 5);  // warp id = (b, j)
    int lane = threadIdx.x & 31;
    int b = gw >> 9, j = gw & 511;
    const float4* ar = (const float4*)(aw + (size_t)j * C_);
    const float4* wr = (const float4*)(w + (size_t)b * C_);
    float s = 0.f;
    #pragma unroll
    for (int i = 0; i < 4; i++) {
        float4 a = ar[lane + 32 * i], x = wr[lane + 32 * i];
        s += a.x * x.x + a.y * x.y + a.z * x.z + a.w * x.w;
    }
    #pragma unroll
    for (int o = 16; o; o >>= 1) s += __shfl_xor_sync(~0u, s, o);
    if (lane == 0) g_styles[gw] = s * 0.04419417382415922f + ab[j];
}

__global__ void k_dcoef(const float* __restrict__ weight) {
    int gw = blockIdx.x * 8 + (threadIdx.x >> 5);  // (b, co)
    int lane = threadIdx.x & 31;
    int b = gw >> 9, co = gw & 511;
    const float* wp = weight + (size_t)co * C_ * 9;
    const float* sp = g_styles + b * C_;
    float s = 0.f;
    #pragma unroll 4
    for (int ci = lane; ci < C_; ci += 32) {
        const float* p = wp + ci * 9;
        float q = 0.f;
        #pragma unroll
        for (int i = 0; i < 9; i++) q += p[i] * p[i];
        float st = sp[ci];
        s += q * st * st;
    }
    #pragma unroll
    for (int o = 16; o; o >>= 1) s += __shfl_xor_sync(~0u, s, o);
    if (lane == 0) g_dcoef[gw] = rsqrtf(s + 1e-8f);
}

// phase-composed 3x3 kernels -> g_pw[ph][tap][co][ci], tf32-rounded
__global__ void k_pw(const float* __restrict__ weight) {
    int co = blockIdx.x, ci = threadIdx.x;
    const float* p = weight + ((size_t)co * C_ + ci) * 9;
    float wgt[3][3];
    #pragma unroll
    for (int sy = 0; sy < 3; sy++)
        #pragma unroll
        for (int sx = 0; sx < 3; sx++) wgt[sy][sx] = p[sy * 3 + sx];
    const float cc[4] = {1.f, 3.f, 3.f, 1.f};
    #pragma unroll
    for (int ry = 0; ry < 2; ry++)
    #pragma unroll
    for (int rx = 0; rx < 2; rx++) {
        int ph = ry * 2 + rx;
        #pragma unroll
        for (int dyi = 0; dyi < 3; dyi++)
        #pragma unroll
        for (int dxi = 0; dxi < 3; dxi++) {
            float v = 0.f;
            #pragma unroll
            for (int sy = 0; sy < 3; sy++) {
                int uy = 2 * dyi + 1 - ry - sy;
                if (uy < 0 || uy > 3) continue;
                #pragma unroll
                for (int sx = 0; sx < 3; sx++) {
                    int ux = 2 * dxi + 1 - rx - sx;
                    if (ux < 0 || ux > 3) continue;
                    v += wgt[2 - sy][2 - sx] * cc[uy] * cc[ux];
                }
            }
            int tap = dyi * 3 + dxi;
            g_pw[(((size_t)(ph * 9 + tap) * C_) + co) * C_ + ci] = to_tf32(v * 0.0625f);
        }
    }
}

__global__ void k_xs(const float* __restrict__ x) {
    int bc = blockIdx.x;                       // b*512+ci
    float st = g_styles[bc];
    const float4* src = (const float4*)(x + (size_t)bc * (HIN * HIN));
    float4* dst = (float4*)(g_xs + (size_t)bc * (HIN * HIN));
    float4 v = src[threadIdx.x];
    v.x = to_tf32(v.x * st); v.y = to_tf32(v.y * st);
    v.z = to_tf32(v.z * st); v.w = to_tf32(v.w * st);
    dst[threadIdx.x] = v;
}

// ======================= main MMA conv =====================================
// CTA 128co x 256px (8 q-rows), 512 threads (16 warps, 4M x 4N), warp 32x64.
// K loop: 64 chunks of 8 ci; per chunk all 9 taps from raw xs tile in smem.
#define KC    8
#define NCH   64
#define ACO   12                      // A co stride (floats), bank-clean
#define A_FLOATS (9 * 128 * ACO)      // 13824
#define BCI   344                     // B ci stride (floats): 10*34 padded
#define B_FLOATS (KC * BCI)           // 2752
#define BUF_FLOATS (A_FLOATS + B_FLOATS)   // 16576
#define BUF_BYTES  (BUF_FLOATS * 4)        // 66304
#define SMEM_DYN   (2 * BUF_BYTES)         // 132608

__global__ void __launch_bounds__(512, 1)
k_conv_mma(const float* __restrict__ bias,
           const float* __restrict__ noise,
           const float* __restrict__ nstr,
           float* __restrict__ out) {
    extern __shared__ float dsm[];
    const uint32_t sbase = smem_u32(dsm);

    const int tid  = threadIdx.x;
    const int lane = tid & 31;
    const int wid  = tid >> 5;
    const int wm   = (wid & 3) * 32;          // warp co offset
    const int wn   = (wid >> 2) * 64;         // warp pix offset
    const int g    = lane >> 2;               // groupID
    const int tg   = lane & 3;                // thread-in-group

    const int co0 = blockIdx.x * 128;
    const int qy0 = blockIdx.y * 8;           // 8 q-rows per CTA
    const int bz  = blockIdx.z;
    const int b   = bz >> 2, ph = bz & 3;
    const int ry  = ph >> 1, rx = ph & 1;

    const float* xs_b = g_xs + (size_t)b * C_ * (HIN * HIN);
    const float* pw_p = g_pw + (size_t)ph * 9 * C_ * C_;

    float acc[2][8][4];
    #pragma unroll
    for (int mf = 0; mf < 2; mf++)
        #pragma unroll
        for (int nf = 0; nf < 8; nf++)
            #pragma unroll
            for (int r = 0; r < 4; r++) acc[mf][nf][r] = 0.f;

    // ---- chunk loader (cp.async into buffer p) ----
    auto load_chunk = [&](int it, int p) {
        const int ci0 = it * KC;
        const uint32_t ab = sbase + p * BUF_BYTES;
        const uint32_t bb = ab + A_FLOATS * 4;
        // A: 9 taps x 128 co x 8 ci  (2304 float4; smem co-stride 12)
        #pragma unroll
        for (int j = 0; j < 5; j++) {
            int f4 = j * 512 + tid;
            if (j == 4 && f4 >= 2304) break;
            int row  = f4 >> 1;               // tap*128 + co  (0..1151)
            int half = f4 & 1;                // ci half (0..1)
            int tap  = row >> 7;
            int co   = row & 127;
            cp16(ab + (uint32_t)((row * ACO + half * 4) * 4),
                 pw_p + ((size_t)tap * C_ + co0 + co) * C_ + ci0 + half * 4);
        }
        // B: raw xs, 8 ci x 10 rows x 34 cols (zero-filled halo)
        #pragma unroll
        for (int j = 0; j < 6; j++) {
            int e = j * 512 + tid;
            if (j == 5 && e >= 2720) break;
            int ci  = e / 340;
            int rem = e - ci * 340;
            int row = rem / 34;
            int col = rem - row * 34;
            int gy = qy0 + row - 1;
            int gx = col - 1;
            bool ok = ((unsigned)gy < (unsigned)HIN) & ((unsigned)gx < (unsigned)HIN);
            cp4z(bb + (uint32_t)((ci * BCI + row * 34 + col) * 4),
                 xs_b + (size_t)(ci0 + ci) * (HIN * HIN) + gy * HIN + gx, ok);
        }
    };

    load_chunk(0, 0);
    CP_COMMIT();

    for (int it = 0; it < NCH; ++it) {
        const int p = it & 1;
        CP_WAIT0();
        __syncthreads();
        if (it + 1 < NCH) { load_chunk(it + 1, p ^ 1); CP_COMMIT(); }

        const float* sA = dsm + p * BUF_FLOATS;
        const float* sB = sA + A_FLOATS;

        #pragma unroll
        for (int tap = 0; tap < 9; tap++) {
            const int dy = tap / 3, dx = tap - 3 * (tap / 3);
            const float* at = sA + tap * (128 * ACO);
            float af[2][4];
            #pragma unroll
            for (int mf = 0; mf < 2; mf++) {
                int r0 = wm + mf * 16 + g;
                af[mf][0] = at[r0 * ACO + tg];
                af[mf][1] = at[(r0 + 8) * ACO + tg];
                af[mf][2] = at[r0 * ACO + tg + 4];
                af[mf][3] = at[(r0 + 8) * ACO + tg + 4];
            }
            #pragma unroll
            for (int nf = 0; nf < 8; nf++) {
                int n  = wn + nf * 8 + g;          // pixel col for B frag
                int sy = (n >> 5) + dy;            // smem row (halo-adjusted)
                int sx = (n & 31) + dx;
                float bf[2];
                bf[0] = sB[tg * BCI + sy * 34 + sx];
                bf[1] = sB[(tg + 4) * BCI + sy * 34 + sx];
                mma8(acc[0][nf], af[0], bf);
                mma8(acc[1][nf], af[1], bf);
            }
        }
    }

    // ---- epilogue: demod + noise + bias + lrelu*sqrt(2) ----
    const float ns = *nstr;
    #pragma unroll
    for (int mf = 0; mf < 2; mf++) {
        int co_a = co0 + wm + mf * 16 + g;
        int co_b = co_a + 8;
        float dca = g_dcoef[b * C_ + co_a], bva = bias[co_a];
        float dcb = g_dcoef[b * C_ + co_b], bvb = bias[co_b];
        float* oa = out + ((size_t)(b * C_ + co_a) * RESO) * RESO;
        float* ob = out + ((size_t)(b * C_ + co_b) * RESO) * RESO;
        #pragma unroll
        for (int nf = 0; nf < 8; nf++) {
            int n0 = wn + nf * 8 + 2 * tg;
            int oy = 2 * (qy0 + (n0 >> 5)) + ry;
            int ox = 2 * (n0 & 31) + rx;
            int base = oy * RESO + ox;
            float nz0 = noise[base] * ns;
            float nz1 = noise[base + 2] * ns;
            float v0 = acc[mf][nf][0] * dca + nz0 + bva;
            float v1 = acc[mf][nf][1] * dca + nz1 + bva;
            float v2 = acc[mf][nf][2] * dcb + nz0 + bvb;
            float v3 = acc[mf][nf][3] * dcb + nz1 + bvb;
            v0 = (v0 >= 0.f ? v0 : 0.2f * v0) * 1.4142135623730951f;
            v1 = (v1 >= 0.f ? v1 : 0.2f * v1) * 1.4142135623730951f;
            v2 = (v2 >= 0.f ? v2 : 0.2f * v2) * 1.4142135623730951f;
            v3 = (v3 >= 0.f ? v3 : 0.2f * v3) * 1.4142135623730951f;
            oa[base]     = v0;
            oa[base + 2] = v1;
            ob[base]     = v2;
            ob[base + 2] = v3;
        }
    }
}

// ======================= launch ============================================
extern "C" void kernel_launch(void* const* d_in, const int* in_sizes, int n_in,
                              void* d_out, int out_size) {
    const float* x      = (const float*)d_in[0];
    const float* w      = (const float*)d_in[1];
    const float* aw     = (const float*)d_in[2];
    const float* ab     = (const float*)d_in[3];
    const float* weight = (const float*)d_in[4];
    const float* bias   = (const float*)d_in[5];
    const float* noise  = (const float*)d_in[6];
    const float* nstr   = (const float*)d_in[7];
    float* out = (float*)d_out;

    static bool attr_set = false;
    if (!attr_set) {
        cudaFuncSetAttribute(k_conv_mma,
                             cudaFuncAttributeMaxDynamicSharedMemorySize, SMEM_DYN);
        attr_set = true;
    }

    k_styles<<<(B_ * C_) / 8, 256>>>(w, aw, ab);
    k_pw<<<C_, C_>>>(weight);
    k_dcoef<<<(B_ * C_) / 8, 256>>>(weight);
    k_xs<<<B_ * C_, (HIN * HIN) / 4>>>(x);
    k_conv_mma<<<dim3(4, 4, B_ * 4), 512, SMEM_DYN>>>(bias, noise, nstr, out);
}

// round 5
// speedup vs baseline: 6.1871x; 1.0419x over previous
#include <cuda_runtime.h>
#include <cuda.h>
#include <cstdint>

// ---------------------------------------------------------------------------
// SynthesisLayer on GB300 — mma.sync tf32 implicit GEMM, raw-xs smem with
// tap shifts applied at fragment-load time; 64x64 warp tile, 3-stage cp.async.
// ---------------------------------------------------------------------------

#define B_    16
#define C_    512
#define HIN   32
#define RESO  64

__device__ float g_styles[B_ * C_];
__device__ float g_dcoef [B_ * C_];
__device__ float g_pw    [4 * 9 * C_ * C_];              // [ph][tap][co][ci], tf32-rounded
__device__ float g_xs    [(size_t)B_ * C_ * HIN * HIN];  // modulated input, tf32-rounded

__device__ __forceinline__ float to_tf32(float x) {
    float y;
    asm("cvt.rna.tf32.f32 %0, %1;" : "=f"(y) : "f"(x));
    return y;
}
__device__ __forceinline__ uint32_t smem_u32(const void* p) {
    uint32_t a;
    asm("{ .reg .u64 t; cvta.to.shared.u64 t, %1; cvt.u32.u64 %0, t; }"
        : "=r"(a) : "l"(p));
    return a;
}
__device__ __forceinline__ void cp16(uint32_t dst, const void* src) {
    asm volatile("cp.async.cg.shared.global [%0], [%1], 16;" :: "r"(dst), "l"(src));
}
__device__ __forceinline__ void cp4z(uint32_t dst, const void* src, bool valid) {
    int sz = valid ? 4 : 0;
    asm volatile("cp.async.ca.shared.global [%0], [%1], 4, %2;"
                 :: "r"(dst), "l"(src), "r"(sz));
}
#define CP_COMMIT() asm volatile("cp.async.commit_group;" ::: "memory")
#define CP_WAIT1()  asm volatile("cp.async.wait_group 1;" ::: "memory")
#define CP_WAIT0()  asm volatile("cp.async.wait_group 0;" ::: "memory")

__device__ __forceinline__ void mma8(float* d, const float* a, const float* b) {
    asm volatile(
        "mma.sync.aligned.m16n8k8.row.col.f32.tf32.tf32.f32 "
        "{%0,%1,%2,%3}, {%4,%5,%6,%7}, {%8,%9}, {%0,%1,%2,%3};"
        : "+f"(d[0]), "+f"(d[1]), "+f"(d[2]), "+f"(d[3])
        : "r"(__float_as_uint(a[0])), "r"(__float_as_uint(a[1])),
          "r"(__float_as_uint(a[2])), "r"(__float_as_uint(a[3])),
          "r"(__float_as_uint(b[0])), "r"(__float_as_uint(b[1])));
}

// ======================= setup kernels =====================================
__global__ void k_styles(const float* __restrict__ w,
                         const float* __restrict__ aw,
                         const float* __restrict__ ab) {
    int gw = blockIdx.x * 8 + (threadIdx.x >> 5);  // warp id = (b, j)
    int lane = threadIdx.x & 31;
    int b = gw >> 9, j = gw & 511;
    const float4* ar = (const float4*)(aw + (size_t)j * C_);
    const float4* wr = (const float4*)(w + (size_t)b * C_);
    float s = 0.f;
    #pragma unroll
    for (int i = 0; i < 4; i++) {
        float4 a = ar[lane + 32 * i], x = wr[lane + 32 * i];
        s += a.x * x.x + a.y * x.y + a.z * x.z + a.w * x.w;
    }
    #pragma unroll
    for (int o = 16; o; o >>= 1) s += __shfl_xor_sync(~0u, s, o);
    if (lane == 0) g_styles[gw] = s * 0.04419417382415922f + ab[j];
}

__global__ void k_dcoef(const float* __restrict__ weight) {
    int gw = blockIdx.x * 8 + (threadIdx.x >> 5);  // (b, co)
    int lane = threadIdx.x & 31;
    int b = gw >> 9, co = gw & 511;
    const float* wp = weight + (size_t)co * C_ * 9;
    const float* sp = g_styles + b * C_;
    float s = 0.f;
    #pragma unroll 4
    for (int ci = lane; ci < C_; ci += 32) {
        const float* p = wp + ci * 9;
        float q = 0.f;
        #pragma unroll
        for (int i = 0; i < 9; i++) q += p[i] * p[i];
        float st = sp[ci];
        s += q * st * st;
    }
    #pragma unroll
    for (int o = 16; o; o >>= 1) s += __shfl_xor_sync(~0u, s, o);
    if (lane == 0) g_dcoef[gw] = rsqrtf(s + 1e-8f);
}

// phase-composed 3x3 kernels -> g_pw[ph][tap][co][ci], tf32-rounded
__global__ void k_pw(const float* __restrict__ weight) {
    int co = blockIdx.x, ci = threadIdx.x;
    const float* p = weight + ((size_t)co * C_ + ci) * 9;
    float wgt[3][3];
    #pragma unroll
    for (int sy = 0; sy < 3; sy++)
        #pragma unroll
        for (int sx = 0; sx < 3; sx++) wgt[sy][sx] = p[sy * 3 + sx];
    const float cc[4] = {1.f, 3.f, 3.f, 1.f};
    #pragma unroll
    for (int ry = 0; ry < 2; ry++)
    #pragma unroll
    for (int rx = 0; rx < 2; rx++) {
        int ph = ry * 2 + rx;
        #pragma unroll
        for (int dyi = 0; dyi < 3; dyi++)
        #pragma unroll
        for (int dxi = 0; dxi < 3; dxi++) {
            float v = 0.f;
            #pragma unroll
            for (int sy = 0; sy < 3; sy++) {
                int uy = 2 * dyi + 1 - ry - sy;
                if (uy < 0 || uy > 3) continue;
                #pragma unroll
                for (int sx = 0; sx < 3; sx++) {
                    int ux = 2 * dxi + 1 - rx - sx;
                    if (ux < 0 || ux > 3) continue;
                    v += wgt[2 - sy][2 - sx] * cc[uy] * cc[ux];
                }
            }
            int tap = dyi * 3 + dxi;
            g_pw[(((size_t)(ph * 9 + tap) * C_) + co) * C_ + ci] = to_tf32(v * 0.0625f);
        }
    }
}

__global__ void k_xs(const float* __restrict__ x) {
    int bc = blockIdx.x;                       // b*512+ci
    float st = g_styles[bc];
    const float4* src = (const float4*)(x + (size_t)bc * (HIN * HIN));
    float4* dst = (float4*)(g_xs + (size_t)bc * (HIN * HIN));
    float4 v = src[threadIdx.x];
    v.x = to_tf32(v.x * st); v.y = to_tf32(v.y * st);
    v.z = to_tf32(v.z * st); v.w = to_tf32(v.w * st);
    dst[threadIdx.x] = v;
}

// ======================= main MMA conv =====================================
// CTA 128co x 256px (8 q-rows), 256 threads (8 warps, 2M x 4N), warp 64x64.
// K loop: 64 chunks of 8 ci; per chunk all 9 taps from raw xs tile in smem.
// 3-stage cp.async pipeline (wait_group 1).
#define KC    8
#define NCH   64
#define ACO   12                      // A co stride (floats), bank-clean
#define A_FLOATS (9 * 128 * ACO)      // 13824
#define BCI   344                     // B ci stride (floats): 10*34 padded
#define B_FLOATS (KC * BCI)           // 2752
#define BUF_FLOATS (A_FLOATS + B_FLOATS)   // 16576
#define BUF_BYTES  (BUF_FLOATS * 4)        // 66304
#define NSTAGE 3
#define SMEM_DYN   (NSTAGE * BUF_BYTES)    // 198912

__global__ void __launch_bounds__(256, 1)
k_conv_mma(const float* __restrict__ bias,
           const float* __restrict__ noise,
           const float* __restrict__ nstr,
           float* __restrict__ out) {
    extern __shared__ float dsm[];
    const uint32_t sbase = smem_u32(dsm);

    const int tid  = threadIdx.x;
    const int lane = tid & 31;
    const int wid  = tid >> 5;
    const int wm   = (wid & 1) * 64;          // warp co offset
    const int wn   = (wid >> 1) * 64;         // warp pix offset
    const int g    = lane >> 2;               // groupID
    const int tg   = lane & 3;                // thread-in-group

    const int co0 = blockIdx.x * 128;
    const int qy0 = blockIdx.y * 8;           // 8 q-rows per CTA
    const int bz  = blockIdx.z;
    const int b   = bz >> 2, ph = bz & 3;
    const int ry  = ph >> 1, rx = ph & 1;

    const float* xs_b = g_xs + (size_t)b * C_ * (HIN * HIN);
    const float* pw_p = g_pw + (size_t)ph * 9 * C_ * C_;

    float acc[4][8][4];
    #pragma unroll
    for (int mf = 0; mf < 4; mf++)
        #pragma unroll
        for (int nf = 0; nf < 8; nf++)
            #pragma unroll
            for (int r = 0; r < 4; r++) acc[mf][nf][r] = 0.f;

    // ---- chunk loader (cp.async into stage s) ----
    auto load_chunk = [&](int it, int s) {
        const int ci0 = it * KC;
        const uint32_t ab = sbase + s * BUF_BYTES;
        const uint32_t bb = ab + A_FLOATS * 4;
        // A: 9 taps x 128 co x 8 ci  (2304 float4; smem co-stride 12)
        #pragma unroll
        for (int j = 0; j < 9; j++) {
            int f4 = j * 256 + tid;
            int row  = f4 >> 1;               // tap*128 + co  (0..1151)
            int half = f4 & 1;                // ci half (0..1)
            int tap  = row >> 7;
            int co   = row & 127;
            cp16(ab + (uint32_t)((row * ACO + half * 4) * 4),
                 pw_p + ((size_t)tap * C_ + co0 + co) * C_ + ci0 + half * 4);
        }
        // B: raw xs, 8 ci x 10 rows x 34 cols (zero-filled halo)
        #pragma unroll
        for (int j = 0; j < 11; j++) {
            int e = j * 256 + tid;
            if (j == 10 && e >= 2720) break;
            int ci  = e / 340;
            int rem = e - ci * 340;
            int row = rem / 34;
            int col = rem - row * 34;
            int gy = qy0 + row - 1;
            int gx = col - 1;
            bool ok = ((unsigned)gy < (unsigned)HIN) & ((unsigned)gx < (unsigned)HIN);
            cp4z(bb + (uint32_t)((ci * BCI + row * 34 + col) * 4),
                 xs_b + (size_t)(ci0 + ci) * (HIN * HIN) + gy * HIN + gx, ok);
        }
    };

    load_chunk(0, 0); CP_COMMIT();
    load_chunk(1, 1); CP_COMMIT();

    int stage = 0;
    for (int it = 0; it < NCH; ++it) {
        if (it < NCH - 1) CP_WAIT1(); else CP_WAIT0();
        __syncthreads();
        if (it + 2 < NCH) {
            int ns = stage + 2; if (ns >= NSTAGE) ns -= NSTAGE;
            load_chunk(it + 2, ns);
            CP_COMMIT();
        }

        const float* sA = dsm + stage * BUF_FLOATS;
        const float* sB = sA + A_FLOATS;

        #pragma unroll
        for (int tap = 0; tap < 9; tap++) {
            const int dy = tap / 3, dx = tap - 3 * (tap / 3);
            const float* at = sA + tap * (128 * ACO);
            float af[4][4];
            #pragma unroll
            for (int mf = 0; mf < 4; mf++) {
                int r0 = wm + mf * 16 + g;
                af[mf][0] = at[r0 * ACO + tg];
                af[mf][1] = at[(r0 + 8) * ACO + tg];
                af[mf][2] = at[r0 * ACO + tg + 4];
                af[mf][3] = at[(r0 + 8) * ACO + tg + 4];
            }
            #pragma unroll
            for (int nf = 0; nf < 8; nf++) {
                int n  = wn + nf * 8 + g;          // pixel col for B frag
                int sy = (n >> 5) + dy;            // smem row (halo-adjusted)
                int sx = (n & 31) + dx;
                float bf[2];
                bf[0] = sB[tg * BCI + sy * 34 + sx];
                bf[1] = sB[(tg + 4) * BCI + sy * 34 + sx];
                #pragma unroll
                for (int mf = 0; mf < 4; mf++)
                    mma8(acc[mf][nf], af[mf], bf);
            }
        }

        if (++stage >= NSTAGE) stage = 0;
    }

    // ---- epilogue: demod + noise + bias + lrelu*sqrt(2) ----
    const float ns = *nstr;
    #pragma unroll
    for (int mf = 0; mf < 4; mf++) {
        int co_a = co0 + wm + mf * 16 + g;
        int co_b = co_a + 8;
        float dca = g_dcoef[b * C_ + co_a], bva = bias[co_a];
        float dcb = g_dcoef[b * C_ + co_b], bvb = bias[co_b];
        float* oa = out + ((size_t)(b * C_ + co_a) * RESO) * RESO;
        float* ob = out + ((size_t)(b * C_ + co_b) * RESO) * RESO;
        #pragma unroll
        for (int nf = 0; nf < 8; nf++) {
            int n0 = wn + nf * 8 + 2 * tg;
            int oy = 2 * (qy0 + (n0 >> 5)) + ry;
            int ox = 2 * (n0 & 31) + rx;
            int base = oy * RESO + ox;
            float nz0 = noise[base] * ns;
            float nz1 = noise[base + 2] * ns;
            float v0 = acc[mf][nf][0] * dca + nz0 + bva;
            float v1 = acc[mf][nf][1] * dca + nz1 + bva;
            float v2 = acc[mf][nf][2] * dcb + nz0 + bvb;
            float v3 = acc[mf][nf][3] * dcb + nz1 + bvb;
            v0 = (v0 >= 0.f ? v0 : 0.2f * v0) * 1.4142135623730951f;
            v1 = (v1 >= 0.f ? v1 : 0.2f * v1) * 1.4142135623730951f;
            v2 = (v2 >= 0.f ? v2 : 0.2f * v2) * 1.4142135623730951f;
            v3 = (v3 >= 0.f ? v3 : 0.2f * v3) * 1.4142135623730951f;
            oa[base]     = v0;
            oa[base + 2] = v1;
            ob[base]     = v2;
            ob[base + 2] = v3;
        }
    }
}

// ======================= launch ============================================
extern "C" void kernel_launch(void* const* d_in, const int* in_sizes, int n_in,
                              void* d_out, int out_size) {
    const float* x      = (const float*)d_in[0];
    const float* w      = (const float*)d_in[1];
    const float* aw     = (const float*)d_in[2];
    const float* ab     = (const float*)d_in[3];
    const float* weight = (const float*)d_in[4];
    const float* bias   = (const float*)d_in[5];
    const float* noise  = (const float*)d_in[6];
    const float* nstr   = (const float*)d_in[7];
    float* out = (float*)d_out;

    static bool attr_set = false;
    if (!attr_set) {
        cudaFuncSetAttribute(k_conv_mma,
                             cudaFuncAttributeMaxDynamicSharedMemorySize, SMEM_DYN);
        attr_set = true;
    }

    k_styles<<<(B_ * C_) / 8, 256>>>(w, aw, ab);
    k_pw<<<C_, C_>>>(weight);
    k_dcoef<<<(B_ * C_) / 8, 256>>>(weight);
    k_xs<<<B_ * C_, (HIN * HIN) / 4>>>(x);
    k_conv_mma<<<dim3(4, 4, B_ * 4), 256, SMEM_DYN>>>(bias, noise, nstr, out);
}

// round 6
// speedup vs baseline: 11.6407x; 1.8814x over previous
#include <cuda_runtime.h>
#include <cuda_fp16.h>
#include <cuda.h>
#include <cstdint>

// ---------------------------------------------------------------------------
// SynthesisLayer on GB300 — mma.sync fp16 (m16n8k16, f32 acc) implicit GEMM.
// fp16 has the same 10-bit mantissa as tf32 -> same rel_err, 2x throughput.
// Raw-xs smem (ci-pairs packed half2), tap shifts at fragment-load time,
// 64x64 warp tile, 3-stage cp.async pipeline.
// ---------------------------------------------------------------------------

#define B_    16
#define C_    512
#define HIN   32
#define RESO  64

__device__ float    g_styles[B_ * C_];
__device__ float    g_dcoef [B_ * C_];
__device__ __half   g_pwh   [(size_t)4 * 9 * C_ * C_];       // [ph][tap][co][ci]
__device__ uint32_t g_xs2   [(size_t)B_ * (C_/2) * HIN * HIN]; // [b][ci/2][y][x] half2

__device__ __forceinline__ uint32_t smem_u32(const void* p) {
    uint32_t a;
    asm("{ .reg .u64 t; cvta.to.shared.u64 t, %1; cvt.u32.u64 %0, t; }"
        : "=r"(a) : "l"(p));
    return a;
}
__device__ __forceinline__ void cp16(uint32_t dst, const void* src) {
    asm volatile("cp.async.cg.shared.global [%0], [%1], 16;" :: "r"(dst), "l"(src));
}
__device__ __forceinline__ void cp4z(uint32_t dst, const void* src, bool valid) {
    int sz = valid ? 4 : 0;
    asm volatile("cp.async.ca.shared.global [%0], [%1], 4, %2;"
                 :: "r"(dst), "l"(src), "r"(sz));
}
#define CP_COMMIT() asm volatile("cp.async.commit_group;" ::: "memory")
#define CP_WAIT1()  asm volatile("cp.async.wait_group 1;" ::: "memory")
#define CP_WAIT0()  asm volatile("cp.async.wait_group 0;" ::: "memory")

__device__ __forceinline__ void mma16(float* d, const uint32_t* a, const uint32_t* b) {
    asm volatile(
        "mma.sync.aligned.m16n8k16.row.col.f32.f16.f16.f32 "
        "{%0,%1,%2,%3}, {%4,%5,%6,%7}, {%8,%9}, {%0,%1,%2,%3};"
        : "+f"(d[0]), "+f"(d[1]), "+f"(d[2]), "+f"(d[3])
        : "r"(a[0]), "r"(a[1]), "r"(a[2]), "r"(a[3]),
          "r"(b[0]), "r"(b[1]));
}

// ======================= setup kernels =====================================
__global__ void k_styles(const float* __restrict__ w,
                         const float* __restrict__ aw,
                         const float* __restrict__ ab) {
    int gw = blockIdx.x * 8 + (threadIdx.x >> 5);  // warp id = (b, j)
    int lane = threadIdx.x & 31;
    int b = gw >> 9, j = gw & 511;
    const float4* ar = (const float4*)(aw + (size_t)j * C_);
    const float4* wr = (const float4*)(w + (size_t)b * C_);
    float s = 0.f;
    #pragma unroll
    for (int i = 0; i < 4; i++) {
        float4 a = ar[lane + 32 * i], x = wr[lane + 32 * i];
        s += a.x * x.x + a.y * x.y + a.z * x.z + a.w * x.w;
    }
    #pragma unroll
    for (int o = 16; o; o >>= 1) s += __shfl_xor_sync(~0u, s, o);
    if (lane == 0) g_styles[gw] = s * 0.04419417382415922f + ab[j];
}

__global__ void k_dcoef(const float* __restrict__ weight) {
    int gw = blockIdx.x * 8 + (threadIdx.x >> 5);  // (b, co)
    int lane = threadIdx.x & 31;
    int b = gw >> 9, co = gw & 511;
    const float* wp = weight + (size_t)co * C_ * 9;
    const float* sp = g_styles + b * C_;
    float s = 0.f;
    #pragma unroll 4
    for (int ci = lane; ci < C_; ci += 32) {
        const float* p = wp + ci * 9;
        float q = 0.f;
        #pragma unroll
        for (int i = 0; i < 9; i++) q += p[i] * p[i];
        float st = sp[ci];
        s += q * st * st;
    }
    #pragma unroll
    for (int o = 16; o; o >>= 1) s += __shfl_xor_sync(~0u, s, o);
    if (lane == 0) g_dcoef[gw] = rsqrtf(s + 1e-8f);
}

// phase-composed 3x3 kernels -> g_pwh[ph][tap][co][ci] (fp16)
__global__ void k_pw(const float* __restrict__ weight) {
    int co = blockIdx.x, ci = threadIdx.x;
    const float* p = weight + ((size_t)co * C_ + ci) * 9;
    float wgt[3][3];
    #pragma unroll
    for (int sy = 0; sy < 3; sy++)
        #pragma unroll
        for (int sx = 0; sx < 3; sx++) wgt[sy][sx] = p[sy * 3 + sx];
    const float cc[4] = {1.f, 3.f, 3.f, 1.f};
    #pragma unroll
    for (int ry = 0; ry < 2; ry++)
    #pragma unroll
    for (int rx = 0; rx < 2; rx++) {
        int ph = ry * 2 + rx;
        #pragma unroll
        for (int dyi = 0; dyi < 3; dyi++)
        #pragma unroll
        for (int dxi = 0; dxi < 3; dxi++) {
            float v = 0.f;
            #pragma unroll
            for (int sy = 0; sy < 3; sy++) {
                int uy = 2 * dyi + 1 - ry - sy;
                if (uy < 0 || uy > 3) continue;
                #pragma unroll
                for (int sx = 0; sx < 3; sx++) {
                    int ux = 2 * dxi + 1 - rx - sx;
                    if (ux < 0 || ux > 3) continue;
                    v += wgt[2 - sy][2 - sx] * cc[uy] * cc[ux];
                }
            }
            int tap = dyi * 3 + dxi;
            g_pwh[(((size_t)(ph * 9 + tap) * C_) + co) * C_ + ci] =
                __float2half_rn(v * 0.0625f);
        }
    }
}

// modulated input, ci-pairs packed into half2
__global__ void k_xs(const float* __restrict__ x) {
    int bcp = blockIdx.x;                      // b*256 + cp
    int b = bcp >> 8, cp = bcp & 255;
    float st0 = g_styles[b * C_ + 2 * cp];
    float st1 = g_styles[b * C_ + 2 * cp + 1];
    const float* p0 = x + ((size_t)(b * C_ + 2 * cp)) * (HIN * HIN);
    const float* p1 = p0 + HIN * HIN;
    uint32_t* dst = g_xs2 + (size_t)bcp * (HIN * HIN);
    #pragma unroll
    for (int i = threadIdx.x; i < HIN * HIN; i += 256) {
        __half2 h = __floats2half2_rn(p0[i] * st0, p1[i] * st1);
        dst[i] = *(uint32_t*)&h;
    }
}

// ======================= main MMA conv =====================================
// CTA 128co x 256px (8 q-rows), 256 threads (8 warps, 2M x 4N), warp 64x64.
// K loop: 32 chunks of 16 ci (8 half2 pairs); all 9 taps per chunk from raw
// xs tile; 3-stage cp.async.
#define NCH   32
#define ACO2  12                      // A co stride (half2 words), bank-clean
#define A_WORDS (9 * 128 * ACO2)      // 13824 u32
#define BCI2  344                     // B ci-pair plane stride (words)
#define B_WORDS (8 * BCI2)            // 2752 u32
#define BUF_WORDS (A_WORDS + B_WORDS) // 16576
#define BUF_BYTES (BUF_WORDS * 4)     // 66304
#define NSTAGE 3
#define SMEM_DYN (NSTAGE * BUF_BYTES) // 198912

__global__ void __launch_bounds__(256, 1)
k_conv_mma(const float* __restrict__ bias,
           const float* __restrict__ noise,
           const float* __restrict__ nstr,
           float* __restrict__ out) {
    extern __shared__ uint32_t dsm[];
    const uint32_t sbase = smem_u32(dsm);

    const int tid  = threadIdx.x;
    const int lane = tid & 31;
    const int wid  = tid >> 5;
    const int wm   = (wid & 1) * 64;          // warp co offset
    const int wn   = (wid >> 1) * 64;         // warp pix offset
    const int g    = lane >> 2;               // groupID
    const int tg   = lane & 3;                // thread-in-group

    const int co0 = blockIdx.x * 128;
    const int qy0 = blockIdx.y * 8;           // 8 q-rows per CTA
    const int bz  = blockIdx.z;
    const int b   = bz >> 2, ph = bz & 3;
    const int ry  = ph >> 1, rx = ph & 1;

    const uint32_t* xs_b = g_xs2 + (size_t)b * (C_/2) * (HIN * HIN);
    const __half*   pw_p = g_pwh + (size_t)ph * 9 * C_ * C_;

    float acc[4][8][4];
    #pragma unroll
    for (int mf = 0; mf < 4; mf++)
        #pragma unroll
        for (int nf = 0; nf < 8; nf++)
            #pragma unroll
            for (int r = 0; r < 4; r++) acc[mf][nf][r] = 0.f;

    // ---- chunk loader (cp.async into stage s); chunk = 16 ci ----
    auto load_chunk = [&](int it, int s) {
        const int ci0 = it * 16;
        const uint32_t ab = sbase + s * BUF_BYTES;
        const uint32_t bb = ab + A_WORDS * 4;
        // A: 9 taps x 128 co x 16 ci halves (2 x cp16 per row; row stride 12 words)
        #pragma unroll
        for (int j = 0; j < 9; j++) {
            int f4 = j * 256 + tid;           // 0..2303
            int row  = f4 >> 1;               // tap*128 + co
            int half = f4 & 1;                // 16B half of the 32B row
            int tap  = row >> 7;
            int co   = row & 127;
            cp16(ab + (uint32_t)((row * ACO2) * 4 + half * 16),
                 pw_p + ((size_t)tap * C_ + co0 + co) * C_ + ci0 + half * 8);
        }
        // B: raw xs, 8 ci-pairs x 10 rows x 34 cols of half2 (zero-filled halo)
        #pragma unroll
        for (int j = 0; j < 11; j++) {
            int e = j * 256 + tid;
            if (j == 10 && e >= 2720) break;
            int cp  = e / 340;
            int rem = e - cp * 340;
            int row = rem / 34;
            int col = rem - row * 34;
            int gy = qy0 + row - 1;
            int gx = col - 1;
            bool ok = ((unsigned)gy < (unsigned)HIN) & ((unsigned)gx < (unsigned)HIN);
            cp4z(bb + (uint32_t)((cp * BCI2 + row * 34 + col) * 4),
                 xs_b + (size_t)(ci0 / 2 + cp) * (HIN * HIN) + gy * HIN + gx, ok);
        }
    };

    load_chunk(0, 0); CP_COMMIT();
    load_chunk(1, 1); CP_COMMIT();

    int stage = 0;
    for (int it = 0; it < NCH; ++it) {
        if (it < NCH - 1) CP_WAIT1(); else CP_WAIT0();
        __syncthreads();
        if (it + 2 < NCH) {
            int nst = stage + 2; if (nst >= NSTAGE) nst -= NSTAGE;
            load_chunk(it + 2, nst);
            CP_COMMIT();
        }

        const uint32_t* sA = dsm + stage * BUF_WORDS;
        const uint32_t* sB = sA + A_WORDS;

        #pragma unroll
        for (int tap = 0; tap < 9; tap++) {
            const int dy = tap / 3, dx = tap - 3 * (tap / 3);
            const uint32_t* at = sA + tap * (128 * ACO2);
            uint32_t af[4][4];
            #pragma unroll
            for (int mf = 0; mf < 4; mf++) {
                int r0 = wm + mf * 16 + g;
                af[mf][0] = at[r0 * ACO2 + tg];
                af[mf][1] = at[(r0 + 8) * ACO2 + tg];
                af[mf][2] = at[r0 * ACO2 + tg + 4];
                af[mf][3] = at[(r0 + 8) * ACO2 + tg + 4];
            }
            #pragma unroll
            for (int nf = 0; nf < 8; nf++) {
                int n  = wn + nf * 8 + g;          // pixel col for B frag
                int sy = (n >> 5) + dy;            // smem row (halo-adjusted)
                int sx = (n & 31) + dx;
                uint32_t bf[2];
                bf[0] = sB[tg * BCI2 + sy * 34 + sx];
                bf[1] = sB[(tg + 4) * BCI2 + sy * 34 + sx];
                #pragma unroll
                for (int mf = 0; mf < 4; mf++)
                    mma16(acc[mf][nf], af[mf], bf);
            }
        }

        if (++stage >= NSTAGE) stage = 0;
    }

    // ---- epilogue: demod + noise + bias + lrelu*sqrt(2) ----
    const float ns = *nstr;
    #pragma unroll
    for (int mf = 0; mf < 4; mf++) {
        int co_a = co0 + wm + mf * 16 + g;
        int co_b = co_a + 8;
        float dca = g_dcoef[b * C_ + co_a], bva = bias[co_a];
        float dcb = g_dcoef[b * C_ + co_b], bvb = bias[co_b];
        float* oa = out + ((size_t)(b * C_ + co_a) * RESO) * RESO;
        float* ob = out + ((size_t)(b * C_ + co_b) * RESO) * RESO;
        #pragma unroll
        for (int nf = 0; nf < 8; nf++) {
            int n0 = wn + nf * 8 + 2 * tg;
            int oy = 2 * (qy0 + (n0 >> 5)) + ry;
            int ox = 2 * (n0 & 31) + rx;
            int base = oy * RESO + ox;
            float nz0 = noise[base] * ns;
            float nz1 = noise[base + 2] * ns;
            float v0 = acc[mf][nf][0] * dca + nz0 + bva;
            float v1 = acc[mf][nf][1] * dca + nz1 + bva;
            float v2 = acc[mf][nf][2] * dcb + nz0 + bvb;
            float v3 = acc[mf][nf][3] * dcb + nz1 + bvb;
            v0 = (v0 >= 0.f ? v0 : 0.2f * v0) * 1.4142135623730951f;
            v1 = (v1 >= 0.f ? v1 : 0.2f * v1) * 1.4142135623730951f;
            v2 = (v2 >= 0.f ? v2 : 0.2f * v2) * 1.4142135623730951f;
            v3 = (v3 >= 0.f ? v3 : 0.2f * v3) * 1.4142135623730951f;
            oa[base]     = v0;
            oa[base + 2] = v1;
            ob[base]     = v2;
            ob[base + 2] = v3;
        }
    }
}

// ======================= launch ============================================
extern "C" void kernel_launch(void* const* d_in, const int* in_sizes, int n_in,
                              void* d_out, int out_size) {
    const float* x      = (const float*)d_in[0];
    const float* w      = (const float*)d_in[1];
    const float* aw     = (const float*)d_in[2];
    const float* ab     = (const float*)d_in[3];
    const float* weight = (const float*)d_in[4];
    const float* bias   = (const float*)d_in[5];
    const float* noise  = (const float*)d_in[6];
    const float* nstr   = (const float*)d_in[7];
    float* out = (float*)d_out;

    static bool attr_set = false;
    if (!attr_set) {
        cudaFuncSetAttribute(k_conv_mma,
                             cudaFuncAttributeMaxDynamicSharedMemorySize, SMEM_DYN);
        attr_set = true;
    }

    k_styles<<<(B_ * C_) / 8, 256>>>(w, aw, ab);
    k_pw<<<C_, C_>>>(weight);
    k_dcoef<<<(B_ * C_) / 8, 256>>>(weight);
    k_xs<<<B_ * (C_/2), 256>>>(x);
    k_conv_mma<<<dim3(4, 4, B_ * 4), 256, SMEM_DYN>>>(bias, noise, nstr, out);
}

// round 8
// speedup vs baseline: 11.9907x; 1.0301x over previous
#include <cuda_runtime.h>
#include <cuda_fp16.h>
#include <cuda.h>
#include <cstdint>

// ---------------------------------------------------------------------------
// SynthesisLayer on GB300 — mma.sync fp16 (m16n8k16, f32 acc) implicit GEMM.
// Raw-xs smem (ci-pairs packed half2), tap shifts at fragment-load time,
// 64x64 warp tile, K-chunk=32ci, 2-stage cp.async pipeline.
// ---------------------------------------------------------------------------

#define B_    16
#define C_    512
#define HIN   32
#define RESO  64

__device__ float    g_styles[B_ * C_];
__device__ float    g_dcoef [B_ * C_];
__device__ __half   g_pwh   [(size_t)4 * 9 * C_ * C_];         // [ph][tap][co][ci]
__device__ uint32_t g_xs2   [(size_t)B_ * (C_/2) * HIN * HIN]; // [b][ci/2][y][x] half2

__device__ __forceinline__ uint32_t smem_u32(const void* p) {
    uint32_t a;
    asm("{ .reg .u64 t; cvta.to.shared.u64 t, %1; cvt.u32.u64 %0, t; }"
        : "=r"(a) : "l"(p));
    return a;
}
__device__ __forceinline__ void cp16(uint32_t dst, const void* src) {
    asm volatile("cp.async.cg.shared.global [%0], [%1], 16;" :: "r"(dst), "l"(src));
}
__device__ __forceinline__ void cp4z(uint32_t dst, const void* src, bool valid) {
    int sz = valid ? 4 : 0;
    asm volatile("cp.async.ca.shared.global [%0], [%1], 4, %2;"
                 :: "r"(dst), "l"(src), "r"(sz));
}
#define CP_COMMIT() asm volatile("cp.async.commit_group;" ::: "memory")
#define CP_WAIT1()  asm volatile("cp.async.wait_group 1;" ::: "memory")
#define CP_WAIT0()  asm volatile("cp.async.wait_group 0;" ::: "memory")

__device__ __forceinline__ void mma16(float* d, const uint32_t* a, const uint32_t* b) {
    asm volatile(
        "mma.sync.aligned.m16n8k16.row.col.f32.f16.f16.f32 "
        "{%0,%1,%2,%3}, {%4,%5,%6,%7}, {%8,%9}, {%0,%1,%2,%3};"
        : "+f"(d[0]), "+f"(d[1]), "+f"(d[2]), "+f"(d[3])
        : "r"(a[0]), "r"(a[1]), "r"(a[2]), "r"(a[3]),
          "r"(b[0]), "r"(b[1]));
}

// ======================= setup kernels =====================================
__global__ void k_styles(const float* __restrict__ w,
                         const float* __restrict__ aw,
                         const float* __restrict__ ab) {
    int gw = blockIdx.x * 8 + (threadIdx.x >> 5);  // warp id = (b, j)
    int lane = threadIdx.x & 31;
    int b = gw >> 9, j = gw & 511;
    const float4* ar = (const float4*)(aw + (size_t)j * C_);
    const float4* wr = (const float4*)(w + (size_t)b * C_);
    float s = 0.f;
    #pragma unroll
    for (int i = 0; i < 4; i++) {
        float4 a = ar[lane + 32 * i], x = wr[lane + 32 * i];
        s += a.x * x.x + a.y * x.y + a.z * x.z + a.w * x.w;
    }
    #pragma unroll
    for (int o = 16; o; o >>= 1) s += __shfl_xor_sync(~0u, s, o);
    if (lane == 0) g_styles[gw] = s * 0.04419417382415922f + ab[j];
}

__global__ void k_dcoef(const float* __restrict__ weight) {
    int gw = blockIdx.x * 8 + (threadIdx.x >> 5);  // (b, co)
    int lane = threadIdx.x & 31;
    int b = gw >> 9, co = gw & 511;
    const float* wp = weight + (size_t)co * C_ * 9;
    const float* sp = g_styles + b * C_;
    float s = 0.f;
    #pragma unroll 4
    for (int ci = lane; ci < C_; ci += 32) {
        const float* p = wp + ci * 9;
        float q = 0.f;
        #pragma unroll
        for (int i = 0; i < 9; i++) q += p[i] * p[i];
        float st = sp[ci];
        s += q * st * st;
    }
    #pragma unroll
    for (int o = 16; o; o >>= 1) s += __shfl_xor_sync(~0u, s, o);
    if (lane == 0) g_dcoef[gw] = rsqrtf(s + 1e-8f);
}

// phase-composed 3x3 kernels -> g_pwh[ph][tap][co][ci] (fp16)
__global__ void k_pw(const float* __restrict__ weight) {
    int co = blockIdx.x, ci = threadIdx.x;
    const float* p = weight + ((size_t)co * C_ + ci) * 9;
    float wgt[3][3];
    #pragma unroll
    for (int sy = 0; sy < 3; sy++)
        #pragma unroll
        for (int sx = 0; sx < 3; sx++) wgt[sy][sx] = p[sy * 3 + sx];
    const float cc[4] = {1.f, 3.f, 3.f, 1.f};
    #pragma unroll
    for (int ry = 0; ry < 2; ry++)
    #pragma unroll
    for (int rx = 0; rx < 2; rx++) {
        int ph = ry * 2 + rx;
        #pragma unroll
        for (int dyi = 0; dyi < 3; dyi++)
        #pragma unroll
        for (int dxi = 0; dxi < 3; dxi++) {
            float v = 0.f;
            #pragma unroll
            for (int sy = 0; sy < 3; sy++) {
                int uy = 2 * dyi + 1 - ry - sy;
                if (uy < 0 || uy > 3) continue;
                #pragma unroll
                for (int sx = 0; sx < 3; sx++) {
                    int ux = 2 * dxi + 1 - rx - sx;
                    if (ux < 0 || ux > 3) continue;
                    v += wgt[2 - sy][2 - sx] * cc[uy] * cc[ux];
                }
            }
            int tap = dyi * 3 + dxi;
            g_pwh[(((size_t)(ph * 9 + tap) * C_) + co) * C_ + ci] =
                __float2half_rn(v * 0.0625f);
        }
    }
}

// modulated input, ci-pairs packed into half2
__global__ void k_xs(const float* __restrict__ x) {
    int bcp = blockIdx.x;                      // b*256 + cp
    int b = bcp >> 8, cp = bcp & 255;
    float st0 = g_styles[b * C_ + 2 * cp];
    float st1 = g_styles[b * C_ + 2 * cp + 1];
    const float* p0 = x + ((size_t)(b * C_ + 2 * cp)) * (HIN * HIN);
    const float* p1 = p0 + HIN * HIN;
    uint32_t* dst = g_xs2 + (size_t)bcp * (HIN * HIN);
    #pragma unroll
    for (int i = threadIdx.x; i < HIN * HIN; i += 256) {
        __half2 h = __floats2half2_rn(p0[i] * st0, p1[i] * st1);
        dst[i] = *(uint32_t*)&h;
    }
}

// ======================= main MMA conv =====================================
// CTA 128co x 256px (8 q-rows), 256 threads (8 warps, 2M x 4N), warp 64x64.
// K loop: 16 chunks of 32 ci (16 half2 planes); all 9 taps per chunk from raw
// xs tile; 2-stage cp.async.
#define NCH   16
#define ACO2  20                      // A co stride (words): 16 data + 4 pad
#define A_WORDS (9 * 128 * ACO2)      // 23040 u32
#define BCI2  344                     // B ci-pair plane stride (words)
#define B_WORDS (16 * BCI2)           // 5504 u32
#define BUF_WORDS (A_WORDS + B_WORDS) // 28544
#define BUF_BYTES (BUF_WORDS * 4)     // 114176
#define NSTAGE 2
#define SMEM_DYN (NSTAGE * BUF_BYTES) // 228352

__global__ void __launch_bounds__(256, 1)
k_conv_mma(const float* __restrict__ bias,
           const float* __restrict__ noise,
           const float* __restrict__ nstr,
           float* __restrict__ out) {
    extern __shared__ uint32_t dsm[];
    const uint32_t sbase = smem_u32(dsm);

    const int tid  = threadIdx.x;
    const int lane = tid & 31;
    const int wid  = tid >> 5;
    const int wm   = (wid & 1) * 64;          // warp co offset
    const int wn   = (wid >> 1) * 64;         // warp pix offset
    const int g    = lane >> 2;               // groupID
    const int tg   = lane & 3;                // thread-in-group

    const int co0 = blockIdx.x * 128;
    const int qy0 = blockIdx.y * 8;           // 8 q-rows per CTA
    const int bz  = blockIdx.z;
    const int b   = bz >> 2, ph = bz & 3;
    const int ry  = ph >> 1, rx = ph & 1;

    const uint32_t* xs_b = g_xs2 + (size_t)b * (C_/2) * (HIN * HIN);
    const __half*   pw_p = g_pwh + (size_t)ph * 9 * C_ * C_;

    float acc[4][8][4];
    #pragma unroll
    for (int mf = 0; mf < 4; mf++)
        #pragma unroll
        for (int nf = 0; nf < 8; nf++)
            #pragma unroll
            for (int r = 0; r < 4; r++) acc[mf][nf][r] = 0.f;

    // ---- chunk loader (cp.async into stage s); chunk = 32 ci ----
    auto load_chunk = [&](int it, int s) {
        const int ci0 = it * 32;
        const uint32_t ab = sbase + s * BUF_BYTES;
        const uint32_t bb = ab + A_WORDS * 4;
        // A: 9 taps x 128 co x 32 ci (4 cp16 per co-row; row stride 20 words)
        #pragma unroll
        for (int j = 0; j < 18; j++) {
            int idx = j * 256 + tid;          // 0..4607
            int row = idx >> 2;               // tap*128 + co
            int h   = idx & 3;                // 16B quarter of 64B row
            int tap = row >> 7;
            int co  = row & 127;
            cp16(ab + (uint32_t)((row * ACO2 + h * 4) * 4),
                 pw_p + ((size_t)tap * C_ + co0 + co) * C_ + ci0 + h * 8);
        }
        // B: raw xs, 16 ci-pairs x 10 rows x 34 cols half2 (zero-filled halo)
        #pragma unroll
        for (int j = 0; j < 22; j++) {
            int e = j * 256 + tid;
            if (j == 21 && e >= 5440) break;
            int cp  = e / 340;
            int rem = e - cp * 340;
            int row = rem / 34;
            int col = rem - row * 34;
            int gy = qy0 + row - 1;
            int gx = col - 1;
            bool ok = ((unsigned)gy < (unsigned)HIN) & ((unsigned)gx < (unsigned)HIN);
            cp4z(bb + (uint32_t)((cp * BCI2 + row * 34 + col) * 4),
                 xs_b + (size_t)(ci0 / 2 + cp) * (HIN * HIN) + gy * HIN + gx, ok);
        }
    };

    load_chunk(0, 0); CP_COMMIT();

    int stage = 0;
    for (int it = 0; it < NCH; ++it) {
        __syncthreads();                      // stage^1 free (compute it-1 done)
        if (it + 1 < NCH) {
            load_chunk(it + 1, stage ^ 1);
            CP_COMMIT();
            CP_WAIT1();
        } else {
            CP_WAIT0();
        }
        __syncthreads();                      // stage data visible

        const uint32_t* sA = dsm + stage * BUF_WORDS;
        const uint32_t* sB = sA + A_WORDS;

        #pragma unroll
        for (int tap = 0; tap < 9; tap++) {
            const int dy = tap / 3, dx = tap - 3 * (tap / 3);
            const uint32_t* at = sA + tap * (128 * ACO2);
            uint32_t af[4][8];
            #pragma unroll
            for (int mf = 0; mf < 4; mf++) {
                int r0 = wm + mf * 16 + g;
                const uint32_t* p0 = at + r0 * ACO2 + tg;
                const uint32_t* p1 = at + (r0 + 8) * ACO2 + tg;
                af[mf][0] = p0[0];  af[mf][1] = p1[0];
                af[mf][2] = p0[4];  af[mf][3] = p1[4];
                af[mf][4] = p0[8];  af[mf][5] = p1[8];
                af[mf][6] = p0[12]; af[mf][7] = p1[12];
            }
            #pragma unroll
            for (int nf = 0; nf < 8; nf++) {
                int n  = wn + nf * 8 + g;          // pixel col for B frag
                int sy = (n >> 5) + dy;            // smem row (halo-adjusted)
                int off = sy * 34 + (n & 31) + dx;
                uint32_t bf[4];
                bf[0] = sB[tg * BCI2 + off];
                bf[1] = sB[(tg + 4) * BCI2 + off];
                bf[2] = sB[(tg + 8) * BCI2 + off];
                bf[3] = sB[(tg + 12) * BCI2 + off];
                #pragma unroll
                for (int mf = 0; mf < 4; mf++) {
                    mma16(acc[mf][nf], af[mf], bf);
                    mma16(acc[mf][nf], af[mf] + 4, bf + 2);
                }
            }
        }

        stage ^= 1;
    }

    // ---- epilogue: demod + noise + bias + lrelu*sqrt(2) ----
    const float ns = *nstr;
    #pragma unroll
    for (int mf = 0; mf < 4; mf++) {
        int co_a = co0 + wm + mf * 16 + g;
        int co_b = co_a + 8;
        float dca = g_dcoef[b * C_ + co_a], bva = bias[co_a];
        float dcb = g_dcoef[b * C_ + co_b], bvb = bias[co_b];
        float* oa = out + ((size_t)(b * C_ + co_a) * RESO) * RESO;
        float* ob = out + ((size_t)(b * C_ + co_b) * RESO) * RESO;
        #pragma unroll
        for (int nf = 0; nf < 8; nf++) {
            int n0 = wn + nf * 8 + 2 * tg;
            int oy = 2 * (qy0 + (n0 >> 5)) + ry;
            int ox = 2 * (n0 & 31) + rx;
            int base = oy * RESO + ox;
            float nz0 = noise[base] * ns;
            float nz1 = noise[base + 2] * ns;
            float v0 = acc[mf][nf][0] * dca + nz0 + bva;
            float v1 = acc[mf][nf][1] * dca + nz1 + bva;
            float v2 = acc[mf][nf][2] * dcb + nz0 + bvb;
            float v3 = acc[mf][nf][3] * dcb + nz1 + bvb;
            v0 = (v0 >= 0.f ? v0 : 0.2f * v0) * 1.4142135623730951f;
            v1 = (v1 >= 0.f ? v1 : 0.2f * v1) * 1.4142135623730951f;
            v2 = (v2 >= 0.f ? v2 : 0.2f * v2) * 1.4142135623730951f;
            v3 = (v3 >= 0.f ? v3 : 0.2f * v3) * 1.4142135623730951f;
            oa[base]     = v0;
            oa[base + 2] = v1;
            ob[base]     = v2;
            ob[base + 2] = v3;
        }
    }
}

// ======================= launch ============================================
extern "C" void kernel_launch(void* const* d_in, const int* in_sizes, int n_in,
                              void* d_out, int out_size) {
    const float* x      = (const float*)d_in[0];
    const float* w      = (const float*)d_in[1];
    const float* aw     = (const float*)d_in[2];
    const float* ab     = (const float*)d_in[3];
    const float* weight = (const float*)d_in[4];
    const float* bias   = (const float*)d_in[5];
    const float* noise  = (const float*)d_in[6];
    const float* nstr   = (const float*)d_in[7];
    float* out = (float*)d_out;

    static bool attr_set = false;
    if (!attr_set) {
        cudaFuncSetAttribute(k_conv_mma,
                             cudaFuncAttributeMaxDynamicSharedMemorySize, SMEM_DYN);
        attr_set = true;
    }

    k_styles<<<(B_ * C_) / 8, 256>>>(w, aw, ab);
    k_pw<<<C_, C_>>>(weight);
    k_dcoef<<<(B_ * C_) / 8, 256>>>(weight);
    k_xs<<<B_ * (C_/2), 256>>>(x);
    k_conv_mma<<<dim3(4, 4, B_ * 4), 256, SMEM_DYN>>>(bias, noise, nstr, out);
}

// round 10
// speedup vs baseline: 13.4695x; 1.1233x over previous
#include <cuda_runtime.h>
#include <cuda_fp16.h>
#include <cuda.h>
#include <cstdint>

// ---------------------------------------------------------------------------
// SynthesisLayer on GB300 — mma.sync fp16 implicit GEMM, ldmatrix operand
// feeds (A row-major 16x16 x4; B via kp-grouped xs layout, non-trans x4).
// ---------------------------------------------------------------------------

#define B_    16
#define C_    512
#define HIN   32
#define RESO  64

__device__ float    g_styles[B_ * C_];
__device__ float    g_dcoef [B_ * C_];
__device__ float    g_wsq   [C_ * C_];
__device__ __half   g_pwh   [(size_t)4 * 9 * C_ * C_];  // [ph][tap][co][ci]
// xs, kp-grouped: [b][cg=ci/8][y][x][kp=4 half2 words] (16B per (cg,y,x))
__device__ uint32_t g_xs3   [(size_t)B_ * 64 * HIN * HIN * 4];

__device__ __forceinline__ uint32_t smem_u32(const void* p) {
    uint32_t a;
    asm("{ .reg .u64 t; cvta.to.shared.u64 t, %1; cvt.u32.u64 %0, t; }"
        : "=r"(a) : "l"(p));
    return a;
}
__device__ __forceinline__ void cp16(uint32_t dst, const void* src) {
    asm volatile("cp.async.cg.shared.global [%0], [%1], 16;" :: "r"(dst), "l"(src));
}
__device__ __forceinline__ void cp16z(uint32_t dst, const void* src, bool valid) {
    int sz = valid ? 16 : 0;
    asm volatile("cp.async.cg.shared.global [%0], [%1], 16, %2;"
                 :: "r"(dst), "l"(src), "r"(sz));
}
#define CP_COMMIT() asm volatile("cp.async.commit_group;" ::: "memory")
#define CP_WAIT1()  asm volatile("cp.async.wait_group 1;" ::: "memory")
#define CP_WAIT0()  asm volatile("cp.async.wait_group 0;" ::: "memory")

__device__ __forceinline__ void ldsm4(uint32_t* r, uint32_t addr) {
    asm volatile("ldmatrix.sync.aligned.m8n8.x4.shared.b16 {%0,%1,%2,%3}, [%4];"
                 : "=r"(r[0]), "=r"(r[1]), "=r"(r[2]), "=r"(r[3]) : "r"(addr));
}
__device__ __forceinline__ void mma16(float* d, const uint32_t* a, const uint32_t* b) {
    asm volatile(
        "mma.sync.aligned.m16n8k16.row.col.f32.f16.f16.f32 "
        "{%0,%1,%2,%3}, {%4,%5,%6,%7}, {%8,%9}, {%0,%1,%2,%3};"
        : "+f"(d[0]), "+f"(d[1]), "+f"(d[2]), "+f"(d[3])
        : "r"(a[0]), "r"(a[1]), "r"(a[2]), "r"(a[3]),
          "r"(b[0]), "r"(b[1]));
}

// ======================= setup kernels =====================================
__global__ void k_styles(const float* __restrict__ w,
                         const float* __restrict__ aw,
                         const float* __restrict__ ab) {
    int gw = blockIdx.x * 8 + (threadIdx.x >> 5);
    int lane = threadIdx.x & 31;
    int b = gw >> 9, j = gw & 511;
    const float4* ar = (const float4*)(aw + (size_t)j * C_);
    const float4* wr = (const float4*)(w + (size_t)b * C_);
    float s = 0.f;
    #pragma unroll
    for (int i = 0; i < 4; i++) {
        float4 a = ar[lane + 32 * i], x = wr[lane + 32 * i];
        s += a.x * x.x + a.y * x.y + a.z * x.z + a.w * x.w;
    }
    #pragma unroll
    for (int o = 16; o; o >>= 1) s += __shfl_xor_sync(~0u, s, o);
    if (lane == 0) g_styles[gw] = s * 0.04419417382415922f + ab[j];
}

// phase-composed 3x3 kernels (half2-coalesced writes) + wsq table
__global__ void k_pw(const float* __restrict__ weight) {
    int co = blockIdx.x, t = threadIdx.x;    // t = ci pair 0..255
    int ci0 = 2 * t;
    float wgt[2][3][3];
    float wsq[2] = {0.f, 0.f};
    #pragma unroll
    for (int h = 0; h < 2; h++) {
        const float* p = weight + ((size_t)co * C_ + ci0 + h) * 9;
        #pragma unroll
        for (int k = 0; k < 9; k++) {
            float v = p[k];
            wgt[h][k / 3][k % 3] = v;
            wsq[h] += v * v;
        }
    }
    *(float2*)(g_wsq + (size_t)co * C_ + ci0) = make_float2(wsq[0], wsq[1]);
    const float cc[4] = {1.f, 3.f, 3.f, 1.f};
    #pragma unroll
    for (int ry = 0; ry < 2; ry++)
    #pragma unroll
    for (int rx = 0; rx < 2; rx++) {
        int ph = ry * 2 + rx;
        #pragma unroll
        for (int dyi = 0; dyi < 3; dyi++)
        #pragma unroll
        for (int dxi = 0; dxi < 3; dxi++) {
            float v[2] = {0.f, 0.f};
            #pragma unroll
            for (int sy = 0; sy < 3; sy++) {
                int uy = 2 * dyi + 1 - ry - sy;
                if (uy < 0 || uy > 3) continue;
                #pragma unroll
                for (int sx = 0; sx < 3; sx++) {
                    int ux = 2 * dxi + 1 - rx - sx;
                    if (ux < 0 || ux > 3) continue;
                    float c = cc[uy] * cc[ux];
                    v[0] += wgt[0][2 - sy][2 - sx] * c;
                    v[1] += wgt[1][2 - sy][2 - sx] * c;
                }
            }
            int tap = dyi * 3 + dxi;
            __half2 h = __floats2half2_rn(v[0] * 0.0625f, v[1] * 0.0625f);
            *(__half2*)(g_pwh + (((size_t)(ph * 9 + tap) * C_) + co) * C_ + ci0) = h;
        }
    }
}

__global__ void k_dcoef() {
    int gw = blockIdx.x * 8 + (threadIdx.x >> 5);  // (b, co)
    int lane = threadIdx.x & 31;
    int b = gw >> 9, co = gw & 511;
    const float4* wq = (const float4*)(g_wsq + (size_t)co * C_);
    const float4* sp = (const float4*)(g_styles + b * C_);
    float s = 0.f;
    #pragma unroll
    for (int i = 0; i < 4; i++) {
        float4 a = wq[lane + 32 * i], x = sp[lane + 32 * i];
        s += a.x * x.x * x.x + a.y * x.y * x.y + a.z * x.z * x.z + a.w * x.w * x.w;
    }
    #pragma unroll
    for (int o = 16; o; o >>= 1) s += __shfl_xor_sync(~0u, s, o);
    if (lane == 0) g_dcoef[gw] = rsqrtf(s + 1e-8f);
}

// modulated input -> kp-grouped half2 layout
__global__ void k_xs(const float* __restrict__ x) {
    int bg = blockIdx.x;                      // b*64 + cg
    int b = bg >> 6, cg = bg & 63;
    float st[8];
    #pragma unroll
    for (int j = 0; j < 8; j++) st[j] = g_styles[b * C_ + cg * 8 + j];
    const float* src = x + ((size_t)(b * C_ + cg * 8)) * (HIN * HIN);
    uint4* dst = (uint4*)g_xs3 + (size_t)bg * (HIN * HIN);
    for (int i = threadIdx.x; i < HIN * HIN; i += 256) {
        uint4 o;
        __half2 h0 = __floats2half2_rn(src[i] * st[0], src[i + 1024] * st[1]);
        __half2 h1 = __floats2half2_rn(src[i + 2048] * st[2], src[i + 3072] * st[3]);
        __half2 h2 = __floats2half2_rn(src[i + 4096] * st[4], src[i + 5120] * st[5]);
        __half2 h3 = __floats2half2_rn(src[i + 6144] * st[6], src[i + 7168] * st[7]);
        o.x = *(uint32_t*)&h0; o.y = *(uint32_t*)&h1;
        o.z = *(uint32_t*)&h2; o.w = *(uint32_t*)&h3;
        dst[i] = o;
    }
}

// ======================= main MMA conv =====================================
// CTA 128co x 256px (8 q-rows), 256 threads (8 warps, 2M x 4N), warp 64x64.
// K loop: 16 chunks of 32 ci (4 cg groups); ldmatrix operand loads.
#define NCH   16
#define ACO2  20                      // A co stride (words): 16 data + 4 pad
#define A_WORDS (9 * 128 * ACO2)      // 23040 u32
#define A_TAP_BYTES (128 * ACO2 * 4)  // 10240
#define B_WORDS (4 * 340 * 4)         // 5440 u32 (cg x 10 x 34 x kp)
#define BUF_WORDS (A_WORDS + B_WORDS) // 28480
#define BUF_BYTES (BUF_WORDS * 4)     // 113920
#define NSTAGE 2
#define SMEM_DYN (NSTAGE * BUF_BYTES) // 227840

__global__ void __launch_bounds__(256, 1)
k_conv_mma(const float* __restrict__ bias,
           const float* __restrict__ noise,
           const float* __restrict__ nstr,
           float* __restrict__ out) {
    extern __shared__ uint32_t dsm[];
    const uint32_t sbase = smem_u32(dsm);

    const int tid  = threadIdx.x;
    const int lane = tid & 31;
    const int wid  = tid >> 5;
    const int wm   = (wid & 1) * 64;          // warp co offset
    const int wn   = (wid >> 1) * 64;         // warp pix offset
    const int g    = lane >> 2;
    const int tg   = lane & 3;

    const int co0 = blockIdx.x * 128;
    const int qy0 = blockIdx.y * 8;
    const int bz  = blockIdx.z;
    const int b   = bz >> 2, ph = bz & 3;
    const int ry  = ph >> 1, rx = ph & 1;

    const uint32_t* xs_b = g_xs3 + (size_t)(b * 64) * (HIN * HIN * 4);
    const __half*   pw_p = g_pwh + (size_t)ph * 9 * C_ * C_;

    // ldmatrix lane address bases (byte offsets within tile regions)
    const uint32_t a_lane = (uint32_t)((wm + (lane & 15)) * (ACO2 * 4) + (lane >> 4) * 16);
    const uint32_t b_lane = (uint32_t)((lane >> 3) * (340 * 16) + (lane & 7) * 16);

    float acc[4][8][4];
    #pragma unroll
    for (int mf = 0; mf < 4; mf++)
        #pragma unroll
        for (int nf = 0; nf < 8; nf++)
            #pragma unroll
            for (int r = 0; r < 4; r++) acc[mf][nf][r] = 0.f;

    // ---- chunk loader (cp.async into stage s); chunk = 32 ci = 4 cg ----
    auto load_chunk = [&](int it, int s) {
        const int ci0 = it * 32;
        const uint32_t ab = sbase + s * BUF_BYTES;
        const uint32_t bb = ab + A_WORDS * 4;
        // A: 9 taps x 128 co x 32 ci (4 cp16 per co-row; row stride 20 words)
        #pragma unroll
        for (int j = 0; j < 18; j++) {
            int idx = j * 256 + tid;          // 0..4607
            int row = idx >> 2;               // tap*128 + co
            int h   = idx & 3;
            int tap = row >> 7;
            int co  = row & 127;
            cp16(ab + (uint32_t)((row * ACO2 + h * 4) * 4),
                 pw_p + ((size_t)tap * C_ + co0 + co) * C_ + ci0 + h * 8);
        }
        // B: 4 cg x 10 rows x 34 cols, one cp16 per (cg,y,x) position
        #pragma unroll
        for (int j = 0; j < 6; j++) {
            int e = j * 256 + tid;
            if (j == 5 && e >= 1360) break;
            int cg  = e / 340;
            int rem = e - cg * 340;
            int row = rem / 34;
            int col = rem - row * 34;
            int gy = qy0 + row - 1;
            int gx = col - 1;
            bool ok = ((unsigned)gy < (unsigned)HIN) & ((unsigned)gx < (unsigned)HIN);
            cp16z(bb + (uint32_t)((cg * 340 + row * 34 + col) * 16),
                  xs_b + (((size_t)(it * 4 + cg)) * (HIN * HIN) + gy * HIN + gx) * 4, ok);
        }
    };

    load_chunk(0, 0); CP_COMMIT();

    int stage = 0;
    for (int it = 0; it < NCH; ++it) {
        __syncthreads();
        if (it + 1 < NCH) {
            load_chunk(it + 1, stage ^ 1);
            CP_COMMIT();
            CP_WAIT1();
        } else {
            CP_WAIT0();
        }
        __syncthreads();

        const uint32_t sA = sbase + stage * BUF_BYTES;
        const uint32_t sBb = sA + A_WORDS * 4;

        #pragma unroll
        for (int tap = 0; tap < 9; tap++) {
            const int dy = tap / 3, dx = tap - 3 * (tap / 3);
            const uint32_t at = sA + tap * A_TAP_BYTES + a_lane;
            uint32_t af[4][8];
            #pragma unroll
            for (int mf = 0; mf < 4; mf++) {
                ldsm4(af[mf],     at + mf * (16 * ACO2 * 4));        // kseg0
                ldsm4(af[mf] + 4, at + mf * (16 * ACO2 * 4) + 32);   // kseg1
            }
            const uint32_t bt = sBb + b_lane + (uint32_t)((dy * 34 + dx) * 16);
            #pragma unroll
            for (int nf = 0; nf < 8; nf++) {
                int n0 = wn + nf * 8;
                uint32_t bf[4];
                ldsm4(bf, bt + (uint32_t)((((n0 >> 5) * 34) + (n0 & 31)) * 16));
                #pragma unroll
                for (int mf = 0; mf < 4; mf++) {
                    mma16(acc[mf][nf], af[mf], bf);
                    mma16(acc[mf][nf], af[mf] + 4, bf + 2);
                }
            }
        }

        stage ^= 1;
    }

    // ---- epilogue: demod + noise + bias + lrelu*sqrt(2) ----
    const float ns = *nstr;
    #pragma unroll
    for (int mf = 0; mf < 4; mf++) {
        int co_a = co0 + wm + mf * 16 + g;
        int co_b = co_a + 8;
        float dca = g_dcoef[b * C_ + co_a], bva = bias[co_a];
        float dcb = g_dcoef[b * C_ + co_b], bvb = bias[co_b];
        float* oa = out + ((size_t)(b * C_ + co_a) * RESO) * RESO;
        float* ob = out + ((size_t)(b * C_ + co_b) * RESO) * RESO;
        #pragma unroll
        for (int nf = 0; nf < 8; nf++) {
            int n0 = wn + nf * 8 + 2 * tg;
            int oy = 2 * (qy0 + (n0 >> 5)) + ry;
            int ox = 2 * (n0 & 31) + rx;
            int base = oy * RESO + ox;
            float nz0 = noise[base] * ns;
            float nz1 = noise[base + 2] * ns;
            float v0 = acc[mf][nf][0] * dca + nz0 + bva;
            float v1 = acc[mf][nf][1] * dca + nz1 + bva;
            float v2 = acc[mf][nf][2] * dcb + nz0 + bvb;
            float v3 = acc[mf][nf][3] * dcb + nz1 + bvb;
            v0 = (v0 >= 0.f ? v0 : 0.2f * v0) * 1.4142135623730951f;
            v1 = (v1 >= 0.f ? v1 : 0.2f * v1) * 1.4142135623730951f;
            v2 = (v2 >= 0.f ? v2 : 0.2f * v2) * 1.4142135623730951f;
            v3 = (v3 >= 0.f ? v3 : 0.2f * v3) * 1.4142135623730951f;
            oa[base]     = v0;
            oa[base + 2] = v1;
            ob[base]     = v2;
            ob[base + 2] = v3;
        }
    }
}

// ======================= launch ============================================
extern "C" void kernel_launch(void* const* d_in, const int* in_sizes, int n_in,
                              void* d_out, int out_size) {
    const float* x      = (const float*)d_in[0];
    const float* w      = (const float*)d_in[1];
    const float* aw     = (const float*)d_in[2];
    const float* ab     = (const float*)d_in[3];
    const float* weight = (const float*)d_in[4];
    const float* bias   = (const float*)d_in[5];
    const float* noise  = (const float*)d_in[6];
    const float* nstr   = (const float*)d_in[7];
    float* out = (float*)d_out;

    static bool attr_set = false;
    if (!attr_set) {
        cudaFuncSetAttribute(k_conv_mma,
                             cudaFuncAttributeMaxDynamicSharedMemorySize, SMEM_DYN);
        attr_set = true;
    }

    k_styles<<<(B_ * C_) / 8, 256>>>(w, aw, ab);
    k_pw<<<C_, 256>>>(weight);
    k_dcoef<<<(B_ * C_) / 8, 256>>>();
    k_xs<<<B_ * 64, 256>>>(x);
    k_conv_mma<<<dim3(4, 4, B_ * 4), 256, SMEM_DYN>>>(bias, noise, nstr, out);
}